// round 5
// baseline (speedup 1.0000x reference)
#include <cuda_runtime.h>
#include <cuda_fp16.h>
#include <cstdint>

// Problem constants
#define NB 8      // batch
#define NC 64     // channels
#define NN 4096   // H*W
#define ND 8      // qk head dim
#define NDP 16    // padded head dim (K=16 for m16n8k16)
#define TQ 128    // queries per CTA
#define TK 128    // keys per tile
#define THREADS 256
#define SPLIT 2
#define NT (NN / TK / SPLIT)   // 16 key tiles per CTA

#define LOG2E 1.4426950408889634f

// Scratch (__device__ globals; no allocation allowed)
// g_q/g_k: [B, N, 16] fp16, d-index XOR-swizzled by ((n>>2)&1)*8  (32B rows)
//          q is pre-scaled by log2(e) so softmax uses ex2 directly.
// g_v:     [B, N, 64] fp16, c-index XOR-swizzled by (n&7)*8       (128B rows)
__device__ __align__(16) __half g_q[NB * NN * NDP];
__device__ __align__(16) __half g_k[NB * NN * NDP];
__device__ __align__(16) __half g_v[NB * NN * NC];
// split-K partials
__device__ __align__(16) float g_O[SPLIT][NB * NC * NN];   // unnormalized O
__device__ __align__(16) float g_l[SPLIT][NB * NN];        // row sums

// ---------------------------------------------------------------------------
// Inline PTX (sm_80-baseline: ldmatrix + mma.sync + cp.async — no tcgen05)
// ---------------------------------------------------------------------------
__device__ __forceinline__ uint32_t smem_u32(const void* p) {
    uint32_t a;
    asm("{ .reg .u64 t; cvta.to.shared.u64 t, %1; cvt.u32.u64 %0, t; }"
        : "=r"(a) : "l"(p));
    return a;
}

#define LDMATRIX_X4(r0, r1, r2, r3, addr) \
    asm volatile("ldmatrix.sync.aligned.m8n8.x4.shared.b16 {%0,%1,%2,%3}, [%4];" \
                 : "=r"(r0), "=r"(r1), "=r"(r2), "=r"(r3) : "r"(addr))

#define LDMATRIX_X4_T(r0, r1, r2, r3, addr) \
    asm volatile("ldmatrix.sync.aligned.m8n8.x4.trans.shared.b16 {%0,%1,%2,%3}, [%4];" \
                 : "=r"(r0), "=r"(r1), "=r"(r2), "=r"(r3) : "r"(addr))

// f32-accum PV MMA
#define MMA_16816_F16(c0, c1, c2, c3, a0, a1, a2, a3, b0, b1) \
    asm volatile("mma.sync.aligned.m16n8k16.row.col.f32.f16.f16.f32 " \
                 "{%0,%1,%2,%3}, {%4,%5,%6,%7}, {%8,%9}, {%0,%1,%2,%3};" \
                 : "+f"(c0), "+f"(c1), "+f"(c2), "+f"(c3) \
                 : "r"(a0), "r"(a1), "r"(a2), "r"(a3), "r"(b0), "r"(b1))

// f16-accum S MMA: C-fragment (2 x f16x2) == A-fragment k-slot layout (FA2 reuse)
#define MMA_16816_S_F16(d0, d1, a0, a1, a2, a3, b0, b1) \
    asm volatile("mma.sync.aligned.m16n8k16.row.col.f16.f16.f16.f16 " \
                 "{%0,%1}, {%2,%3,%4,%5}, {%6,%7}, {%8,%9};" \
                 : "=r"(d0), "=r"(d1) \
                 : "r"(a0), "r"(a1), "r"(a2), "r"(a3), "r"(b0), "r"(b1), \
                   "r"(0u), "r"(0u))

#define EX2_F16X2(d, a) \
    asm("ex2.approx.f16x2 %0, %1;" : "=r"(d) : "r"(a))
#define HADD2(d, a, b) \
    asm("add.rn.f16x2 %0, %1, %2;" : "=r"(d) : "r"(a), "r"(b))

#define CP_ASYNC16(smem_addr, gptr) \
    asm volatile("cp.async.cg.shared.global [%0], [%1], 16;" \
                 :: "r"(smem_addr), "l"(gptr) : "memory")
#define CP_COMMIT() asm volatile("cp.async.commit_group;" ::: "memory")
#define CP_WAIT(n)  asm volatile("cp.async.wait_group %0;" :: "n"(n) : "memory")

// SMEM layout (static, double-buffered K/V)
#define SM_Q   0                    // 128 x 32B               (4KB)
#define SM_K0  4096                 // 128 x 32B               (4KB)
#define SM_K1  8192
#define SM_V0  12288                // 128 x 128B              (16KB)
#define SM_V1  28672
#define SM_BYTES 45056              // epilogue reuses [0,32KB) as O stage

// ============================================================================
// Kernel 1: 1x1-conv projections -> swizzled fp16 q/k/v (q pre-scaled log2e).
//   64-thread blocks -> 512 CTAs so all 148 SMs are filled (was 128 CTAs).
// ============================================================================
__global__ __launch_bounds__(64) void proj_kernel(
    const float* __restrict__ x,
    const float* __restrict__ wq, const float* __restrict__ bq,
    const float* __restrict__ wk, const float* __restrict__ bk,
    const float* __restrict__ wv, const float* __restrict__ bv) {
    __shared__ float s_wq[ND * NC], s_wk[ND * NC], s_wv[NC * NC];
    __shared__ float s_bq[ND], s_bk[ND], s_bv[NC];

    int tid = threadIdx.x;
    for (int i = tid; i < ND * NC; i += 64) { s_wq[i] = wq[i]; s_wk[i] = wk[i]; }
    for (int i = tid; i < NC * NC; i += 64) s_wv[i] = wv[i];
    if (tid < ND) { s_bq[tid] = bq[tid]; s_bk[tid] = bk[tid]; }
    s_bv[tid] = bv[tid];
    __syncthreads();

    int idx = blockIdx.x * 64 + tid;    // b*NN + n
    int n = idx & (NN - 1);
    int b = idx >> 12;

    const float* xp = x + (size_t)b * NC * NN + n;
    float xc[NC];
#pragma unroll
    for (int c = 0; c < NC; c++) xc[c] = xp[(size_t)c * NN];

    __half* qo = g_q + (size_t)idx * NDP;
    __half* ko = g_k + (size_t)idx * NDP;
    __half* vo = g_v + (size_t)idx * NC;

    int swqk = (n & 4) ? 8 : 0;       // d-swizzle for 32B rows
    int swv  = (n & 7) << 3;          // c-swizzle for 128B rows

#pragma unroll
    for (int o = 0; o < ND; o++) {
        float aq = s_bq[o], ak = s_bk[o];
#pragma unroll
        for (int c = 0; c < NC; c++) {
            aq += s_wq[o * NC + c] * xc[c];
            ak += s_wk[o * NC + c] * xc[c];
        }
        qo[o ^ swqk] = __float2half(aq * LOG2E);   // fold log2e into q
        ko[o ^ swqk] = __float2half(ak);
    }
#pragma unroll
    for (int o = ND; o < NDP; o++) {
        qo[o ^ swqk] = __float2half(0.f);
        ko[o ^ swqk] = __float2half(0.f);
    }

    for (int o = 0; o < NC; o++) {    // keep rolled (I$)
        float av = s_bv[o];
#pragma unroll
        for (int c = 0; c < NC; c++) av += s_wv[o * NC + c] * xc[c];
        vo[o ^ swv] = __float2half(av);
    }
}

// ============================================================================
// Kernel 2: flash attention partial (split-K), fp16 HMMA.
//   S-MMA accumulates in fp16; its C-fragment feeds ex2.approx.f16x2 directly
//   and the results ARE the A-fragment for the PV MMA (no cvt, no repack).
// ============================================================================
__global__ __launch_bounds__(THREADS, 3) void attn_kernel() {
    __shared__ __align__(16) char smem[SM_BYTES];
    uint32_t sb = smem_u32(smem);

    int tid = threadIdx.x;
    int w = tid >> 5, l = tid & 31;
    int lr = l & 7, sub = l >> 3;     // ldmatrix row-in-group / matrix index
    int qr = w * 16;                  // this warp's query rows
    int b = blockIdx.y;
    int z = blockIdx.z;
    int i0 = blockIdx.x * TQ;
    int j_base = z * (NN / SPLIT);

    const uint4* gq4 = reinterpret_cast<const uint4*>(g_q) + (size_t)b * NN * 2 + (size_t)i0 * 2;
    const uint4* gk4 = reinterpret_cast<const uint4*>(g_k) + (size_t)b * NN * 2 + (size_t)j_base * 2;
    const uint4* gv4 = reinterpret_cast<const uint4*>(g_v) + (size_t)b * NN * 8 + (size_t)j_base * 8;

    // prologue: stage Q + tile 0 (buffer 0)
    for (int t = tid; t < 256; t += THREADS)
        CP_ASYNC16(sb + SM_Q + (uint32_t)t * 16, gq4 + t);
    for (int t = tid; t < 256; t += THREADS)
        CP_ASYNC16(sb + SM_K0 + (uint32_t)t * 16, gk4 + t);
    for (int t = tid; t < 1024; t += THREADS)
        CP_ASYNC16(sb + SM_V0 + (uint32_t)t * 16, gv4 + t);
    CP_COMMIT();
    CP_WAIT(0);
    __syncthreads();

    // per-lane ldmatrix addresses for both buffers (swizzles baked in)
    uint32_t qaddr = sb + SM_Q + (uint32_t)(qr + lr + (sub & 1) * 8) * 32
                   + (uint32_t)(((sub >> 1) ^ ((lr >> 2) & 1)) << 4);
    uint32_t koff = (uint32_t)(lr + (sub >> 1) * 8) * 32
                  + (uint32_t)(((sub & 1) ^ ((lr >> 2) & 1)) << 4);
    uint32_t voff = (uint32_t)(lr + (sub & 1) * 8) * 128;
    uint32_t kb2[2] = { sb + SM_K0 + koff, sb + SM_K1 + koff };
    uint32_t vb2[2] = { sb + SM_V0 + voff, sb + SM_V1 + voff };
    int vsub = sub >> 1;

    uint32_t qa0, qa1, qa2, qa3;
    LDMATRIX_X4(qa0, qa1, qa2, qa3, qaddr);

    float o[32];
#pragma unroll
    for (int k = 0; k < 32; k++) o[k] = 0.f;
    float lsum0 = 0.f, lsum1 = 0.f;

    for (int t = 0; t < NT; t++) {
        // prefetch next tile into the other buffer
        if (t + 1 < NT) {
            uint32_t kd = (t & 1) ? SM_K0 : SM_K1;
            uint32_t vd = (t & 1) ? SM_V0 : SM_V1;
            const uint4* gk = gk4 + (t + 1) * 256;
            const uint4* gv = gv4 + (t + 1) * 1024;
            for (int u = tid; u < 256; u += THREADS)
                CP_ASYNC16(sb + kd + (uint32_t)u * 16, gk + u);
            for (int u = tid; u < 1024; u += THREADS)
                CP_ASYNC16(sb + vd + (uint32_t)u * 16, gv + u);
            CP_COMMIT();
        }
        if (t > 0) {
            if (t + 1 < NT) CP_WAIT(1); else CP_WAIT(0);
            __syncthreads();
        }

        uint32_t kbase = kb2[t & 1];
        uint32_t vbase = vb2[t & 1];
        uint32_t acc0 = 0, acc1 = 0;   // f16x2 row-sum accumulators (per tile)

#pragma unroll
        for (int jt = 0; jt < 8; jt++) {           // 16 keys per step
            uint32_t kr0, kr1, kr2, kr3;
            LDMATRIX_X4(kr0, kr1, kr2, kr3, kbase + (uint32_t)jt * 512);

            // S = q'.k in fp16 (C-fragment == A-fragment k-slots)
            uint32_t s01a, s01b, s89a, s89b;
            MMA_16816_S_F16(s01a, s01b, qa0, qa1, qa2, qa3, kr0, kr1);  // keys 0-7
            MMA_16816_S_F16(s89a, s89b, qa0, qa1, qa2, qa3, kr2, kr3);  // keys 8-15

            // P = 2^S directly on the fragments
            uint32_t pa0, pa1, pa2, pa3;
            EX2_F16X2(pa0, s01a);   // row r,   k 0-7 slot
            EX2_F16X2(pa1, s01b);   // row r+8, k 0-7 slot
            EX2_F16X2(pa2, s89a);   // row r,   k 8-15 slot
            EX2_F16X2(pa3, s89b);   // row r+8, k 8-15 slot
            uint32_t h0, h1;
            HADD2(h0, pa0, pa2); HADD2(acc0, acc0, h0);   // rows r
            HADD2(h1, pa1, pa3); HADD2(acc1, acc1, h1);   // rows r+8

            // O += P V over 64 channels
            uint32_t vrow = vbase + (uint32_t)jt * 2048;
#pragma unroll
            for (int ct = 0; ct < 8; ct += 2) {
                uint32_t vr0, vr1, vr2, vr3;
                uint32_t va = vrow + (uint32_t)(((ct + vsub) ^ lr) << 4);
                LDMATRIX_X4_T(vr0, vr1, vr2, vr3, va);
                MMA_16816_F16(o[ct * 4 + 0], o[ct * 4 + 1], o[ct * 4 + 2], o[ct * 4 + 3],
                              pa0, pa1, pa2, pa3, vr0, vr1);
                MMA_16816_F16(o[ct * 4 + 4], o[ct * 4 + 5], o[ct * 4 + 6], o[ct * 4 + 7],
                              pa0, pa1, pa2, pa3, vr2, vr3);
            }
        }

        // flush f16x2 tile sums into f32 (tile sums ~1e2-1e3, far from f16 max)
        {
            float2 f0 = __half22float2(*reinterpret_cast<__half2*>(&acc0));
            float2 f1 = __half22float2(*reinterpret_cast<__half2*>(&acc1));
            lsum0 += f0.x + f0.y;
            lsum1 += f1.x + f1.y;
        }
        __syncthreads();   // all warps done with buffer t before its refill
    }

    // quad reduce row sums (lanes sharing a row)
    lsum0 += __shfl_xor_sync(0xffffffffu, lsum0, 1);
    lsum0 += __shfl_xor_sync(0xffffffffu, lsum0, 2);
    lsum1 += __shfl_xor_sync(0xffffffffu, lsum1, 1);
    lsum1 += __shfl_xor_sync(0xffffffffu, lsum1, 2);

    // write l partials
    float* lp = g_l[z] + (size_t)b * NN + i0;
    if ((l & 3) == 0) {
        lp[qr + (l >> 2)]     = lsum0;
        lp[qr + (l >> 2) + 8] = lsum1;
    }

    // stage O into smem as [c][i] then coalesced float4 writes of the partial
    float* so = reinterpret_cast<float*>(smem);
    int row0 = qr + (l >> 2);
    int cb = (l & 3) * 2;
#pragma unroll
    for (int ct = 0; ct < 8; ct++) {
        int c0 = ct * 8 + cb;
        so[c0 * 128 + row0]           = o[ct * 4 + 0];
        so[(c0 + 1) * 128 + row0]     = o[ct * 4 + 1];
        so[c0 * 128 + row0 + 8]       = o[ct * 4 + 2];
        so[(c0 + 1) * 128 + row0 + 8] = o[ct * 4 + 3];
    }
    __syncthreads();

    float* gO = g_O[z] + (size_t)b * NC * NN + i0;
    const float4* so4 = reinterpret_cast<const float4*>(so);
    for (int t = tid; t < 2048; t += THREADS) {
        int c = t >> 5;
        int i = (t & 31) * 4;
        *reinterpret_cast<float4*>(gO + (size_t)c * NN + i) = so4[t];
    }
}

// ============================================================================
// Kernel 3: combine split-K partials: out = gamma*(O0+O1)/(l0+l1) + x
// ============================================================================
__global__ __launch_bounds__(256) void combine_kernel(
    const float* __restrict__ x,
    const float* __restrict__ gamma,
    float* __restrict__ out) {
    int t = blockIdx.x * 256 + threadIdx.x;          // 512K threads, float4 each
    int b = t >> 16;
    int rem = t & 65535;
    int c = rem >> 10;
    int i = (rem & 1023) << 2;
    size_t oidx = ((size_t)b * NC + c) * NN + i;
    size_t lidx = (size_t)b * NN + i;

    float4 o0 = *reinterpret_cast<const float4*>(&g_O[0][oidx]);
    float4 o1 = *reinterpret_cast<const float4*>(&g_O[1][oidx]);
    float4 l0 = *reinterpret_cast<const float4*>(&g_l[0][lidx]);
    float4 l1 = *reinterpret_cast<const float4*>(&g_l[1][lidx]);
    float4 xr = *reinterpret_cast<const float4*>(&x[oidx]);
    float g = __ldg(gamma);

    float4 r;
    r.x = g * (o0.x + o1.x) / (l0.x + l1.x) + xr.x;
    r.y = g * (o0.y + o1.y) / (l0.y + l1.y) + xr.y;
    r.z = g * (o0.z + o1.z) / (l0.z + l1.z) + xr.z;
    r.w = g * (o0.w + o1.w) / (l0.w + l1.w) + xr.w;
    *reinterpret_cast<float4*>(&out[oidx]) = r;
}

extern "C" void kernel_launch(void* const* d_in, const int* in_sizes, int n_in,
                              void* d_out, int out_size) {
    const float* x     = (const float*)d_in[0];
    const float* wq    = (const float*)d_in[1];
    const float* bq    = (const float*)d_in[2];
    const float* wk    = (const float*)d_in[3];
    const float* bk    = (const float*)d_in[4];
    const float* wv    = (const float*)d_in[5];
    const float* bv    = (const float*)d_in[6];
    const float* gamma = (const float*)d_in[7];
    float* out = (float*)d_out;

    proj_kernel<<<NB * NN / 64, 64>>>(x, wq, bq, wk, bk, wv, bv);
    attn_kernel<<<dim3(NN / TQ, NB, SPLIT), THREADS>>>();
    combine_kernel<<<NB * NC * NN / 4 / 256, 256>>>(x, gamma, out);
}

// round 6
// speedup vs baseline: 1.0752x; 1.0752x over previous
#include <cuda_runtime.h>
#include <cuda_fp16.h>
#include <cstdint>

// Problem constants
#define NB 8      // batch
#define NC 64     // channels
#define NN 4096   // H*W
#define ND 8      // qk head dim
#define NDP 16    // padded head dim (K=16 for m16n8k16)
#define TQ 128    // queries per CTA
#define TK 128    // keys per tile
#define THREADS 256
#define SPLIT 2
#define NT (NN / TK / SPLIT)   // 16 key tiles per CTA

#define LOG2E 1.4426950408889634f

// Scratch (__device__ globals; no allocation allowed)
// g_q/g_k: [B, N, 16] fp16, d-index XOR-swizzled by ((n>>2)&1)*8  (32B rows)
//          q is pre-scaled by log2(e) so softmax uses ex2 directly.
// g_v:     [B, N, 64] fp16, c-index XOR-swizzled by (n&7)*8       (128B rows)
__device__ __align__(16) __half g_q[NB * NN * NDP];
__device__ __align__(16) __half g_k[NB * NN * NDP];
__device__ __align__(16) __half g_v[NB * NN * NC];
// split-K partials (O in fp16: |O| <= ~5e3 << 65504; rel err ~5e-4 only on attn term)
__device__ __align__(16) __half g_O[SPLIT][NB * NC * NN];
__device__ __align__(16) float  g_l[SPLIT][NB * NN];

// ---------------------------------------------------------------------------
// Inline PTX (sm_80-baseline: ldmatrix + mma.sync + cp.async — no tcgen05)
// ---------------------------------------------------------------------------
__device__ __forceinline__ uint32_t smem_u32(const void* p) {
    uint32_t a;
    asm("{ .reg .u64 t; cvta.to.shared.u64 t, %1; cvt.u32.u64 %0, t; }"
        : "=r"(a) : "l"(p));
    return a;
}

#define LDMATRIX_X4(r0, r1, r2, r3, addr) \
    asm volatile("ldmatrix.sync.aligned.m8n8.x4.shared.b16 {%0,%1,%2,%3}, [%4];" \
                 : "=r"(r0), "=r"(r1), "=r"(r2), "=r"(r3) : "r"(addr))

#define LDMATRIX_X4_T(r0, r1, r2, r3, addr) \
    asm volatile("ldmatrix.sync.aligned.m8n8.x4.trans.shared.b16 {%0,%1,%2,%3}, [%4];" \
                 : "=r"(r0), "=r"(r1), "=r"(r2), "=r"(r3) : "r"(addr))

// f32-accum PV MMA
#define MMA_16816_F16(c0, c1, c2, c3, a0, a1, a2, a3, b0, b1) \
    asm volatile("mma.sync.aligned.m16n8k16.row.col.f32.f16.f16.f32 " \
                 "{%0,%1,%2,%3}, {%4,%5,%6,%7}, {%8,%9}, {%0,%1,%2,%3};" \
                 : "+f"(c0), "+f"(c1), "+f"(c2), "+f"(c3) \
                 : "r"(a0), "r"(a1), "r"(a2), "r"(a3), "r"(b0), "r"(b1))

// f16-accum S MMA: C-fragment (2 x f16x2) == A-fragment k-slot layout (FA2 reuse)
#define MMA_16816_S_F16(d0, d1, a0, a1, a2, a3, b0, b1) \
    asm volatile("mma.sync.aligned.m16n8k16.row.col.f16.f16.f16.f16 " \
                 "{%0,%1}, {%2,%3,%4,%5}, {%6,%7}, {%8,%9};" \
                 : "=r"(d0), "=r"(d1) \
                 : "r"(a0), "r"(a1), "r"(a2), "r"(a3), "r"(b0), "r"(b1), \
                   "r"(0u), "r"(0u))

#define EX2_F16X2(d, a) \
    asm("ex2.approx.f16x2 %0, %1;" : "=r"(d) : "r"(a))
#define HADD2(d, a, b) \
    asm("add.rn.f16x2 %0, %1, %2;" : "=r"(d) : "r"(a), "r"(b))

#define CP_ASYNC16(smem_addr, gptr) \
    asm volatile("cp.async.cg.shared.global [%0], [%1], 16;" \
                 :: "r"(smem_addr), "l"(gptr) : "memory")
#define CP_COMMIT() asm volatile("cp.async.commit_group;" ::: "memory")
#define CP_WAIT(n)  asm volatile("cp.async.wait_group %0;" :: "n"(n) : "memory")

// SMEM layout (static, double-buffered K/V)
#define SM_Q   0                    // 128 x 32B               (4KB)
#define SM_K0  4096                 // 128 x 32B               (4KB)
#define SM_K1  8192
#define SM_V0  12288                // 128 x 128B              (16KB)
#define SM_V1  28672
#define SM_BYTES 45056              // epilogue reuses [0,32KB) as O stage

// ============================================================================
// Kernel 1: 1x1-conv projections. Latency-chain fix: 4 independent FMA
// accumulator chains (ILP 4), float4 weight LDS, half2 packed stores.
// ============================================================================
__global__ __launch_bounds__(64) void proj_kernel(
    const float* __restrict__ x,
    const float* __restrict__ wq, const float* __restrict__ bq,
    const float* __restrict__ wk, const float* __restrict__ bk,
    const float* __restrict__ wv, const float* __restrict__ bv) {
    __shared__ float s_wq[ND * NC], s_wk[ND * NC], s_wv[NC * NC];
    __shared__ float s_bq[ND], s_bk[ND], s_bv[NC];

    int tid = threadIdx.x;
    for (int i = tid; i < ND * NC; i += 64) { s_wq[i] = wq[i]; s_wk[i] = wk[i]; }
    for (int i = tid; i < NC * NC; i += 64) s_wv[i] = wv[i];
    if (tid < ND) { s_bq[tid] = bq[tid]; s_bk[tid] = bk[tid]; }
    s_bv[tid] = bv[tid];
    __syncthreads();

    int idx = blockIdx.x * 64 + tid;    // b*NN + n
    int n = idx & (NN - 1);
    int b = idx >> 12;

    const float* xp = x + (size_t)b * NC * NN + n;
    float4 xc[16];                      // x column, 4 channels per reg group
#pragma unroll
    for (int c4 = 0; c4 < 16; c4++) {
        xc[c4].x = xp[(size_t)(4 * c4 + 0) * NN];
        xc[c4].y = xp[(size_t)(4 * c4 + 1) * NN];
        xc[c4].z = xp[(size_t)(4 * c4 + 2) * NN];
        xc[c4].w = xp[(size_t)(4 * c4 + 3) * NN];
    }

    __half* qo = g_q + (size_t)idx * NDP;
    __half* ko = g_k + (size_t)idx * NDP;
    __half* vo = g_v + (size_t)idx * NC;

    int swqk = (n & 4) ? 8 : 0;       // d-swizzle (multiple of 8: pairs survive)
    int swv  = (n & 7) << 3;          // c-swizzle (multiple of 8: pairs survive)

    // q/k: 2 outputs x {q,k} per iter = 4 chains
    for (int o = 0; o < ND; o += 2) {
        float aq0 = s_bq[o], aq1 = s_bq[o + 1];
        float ak0 = s_bk[o], ak1 = s_bk[o + 1];
        const float4* wq0 = reinterpret_cast<const float4*>(s_wq + o * NC);
        const float4* wq1 = reinterpret_cast<const float4*>(s_wq + (o + 1) * NC);
        const float4* wk0 = reinterpret_cast<const float4*>(s_wk + o * NC);
        const float4* wk1 = reinterpret_cast<const float4*>(s_wk + (o + 1) * NC);
#pragma unroll
        for (int c4 = 0; c4 < 16; c4++) {
            float4 xv = xc[c4];
            float4 a;
            a = wq0[c4]; aq0 += a.x * xv.x + a.y * xv.y + a.z * xv.z + a.w * xv.w;
            a = wq1[c4]; aq1 += a.x * xv.x + a.y * xv.y + a.z * xv.z + a.w * xv.w;
            a = wk0[c4]; ak0 += a.x * xv.x + a.y * xv.y + a.z * xv.z + a.w * xv.w;
            a = wk1[c4]; ak1 += a.x * xv.x + a.y * xv.y + a.z * xv.z + a.w * xv.w;
        }
        *reinterpret_cast<__half2*>(qo + (o ^ swqk)) =
            __floats2half2_rn(aq0 * LOG2E, aq1 * LOG2E);
        *reinterpret_cast<__half2*>(ko + (o ^ swqk)) = __floats2half2_rn(ak0, ak1);
    }
    *reinterpret_cast<__half2*>(qo + (8 ^ swqk))  = __half2(__float2half(0.f), __float2half(0.f));
    *reinterpret_cast<__half2*>(qo + (10 ^ swqk)) = __half2(__float2half(0.f), __float2half(0.f));
    *reinterpret_cast<__half2*>(qo + (12 ^ swqk)) = __half2(__float2half(0.f), __float2half(0.f));
    *reinterpret_cast<__half2*>(qo + (14 ^ swqk)) = __half2(__float2half(0.f), __float2half(0.f));
    *reinterpret_cast<__half2*>(ko + (8 ^ swqk))  = __half2(__float2half(0.f), __float2half(0.f));
    *reinterpret_cast<__half2*>(ko + (10 ^ swqk)) = __half2(__float2half(0.f), __float2half(0.f));
    *reinterpret_cast<__half2*>(ko + (12 ^ swqk)) = __half2(__float2half(0.f), __float2half(0.f));
    *reinterpret_cast<__half2*>(ko + (14 ^ swqk)) = __half2(__float2half(0.f), __float2half(0.f));

    // v: 4 output chains per iter (rolled x16 for I$)
    for (int o = 0; o < NC; o += 4) {
        float a0 = s_bv[o], a1 = s_bv[o + 1], a2 = s_bv[o + 2], a3 = s_bv[o + 3];
        const float4* w0 = reinterpret_cast<const float4*>(s_wv + o * NC);
        const float4* w1 = reinterpret_cast<const float4*>(s_wv + (o + 1) * NC);
        const float4* w2 = reinterpret_cast<const float4*>(s_wv + (o + 2) * NC);
        const float4* w3 = reinterpret_cast<const float4*>(s_wv + (o + 3) * NC);
#pragma unroll
        for (int c4 = 0; c4 < 16; c4++) {
            float4 xv = xc[c4];
            float4 a;
            a = w0[c4]; a0 += a.x * xv.x + a.y * xv.y + a.z * xv.z + a.w * xv.w;
            a = w1[c4]; a1 += a.x * xv.x + a.y * xv.y + a.z * xv.z + a.w * xv.w;
            a = w2[c4]; a2 += a.x * xv.x + a.y * xv.y + a.z * xv.z + a.w * xv.w;
            a = w3[c4]; a3 += a.x * xv.x + a.y * xv.y + a.z * xv.z + a.w * xv.w;
        }
        *reinterpret_cast<__half2*>(vo + (o ^ swv))       = __floats2half2_rn(a0, a1);
        *reinterpret_cast<__half2*>(vo + ((o + 2) ^ swv)) = __floats2half2_rn(a2, a3);
    }
}

// ============================================================================
// Kernel 2: flash attention partial (split-K), fp16 HMMA.
//   S-MMA accumulates in fp16; C-fragment feeds ex2.approx.f16x2 directly
//   and the results ARE the A-fragment for the PV MMA (no cvt, no repack).
// ============================================================================
__global__ __launch_bounds__(THREADS, 3) void attn_kernel() {
    __shared__ __align__(16) char smem[SM_BYTES];
    uint32_t sb = smem_u32(smem);

    int tid = threadIdx.x;
    int w = tid >> 5, l = tid & 31;
    int lr = l & 7, sub = l >> 3;     // ldmatrix row-in-group / matrix index
    int qr = w * 16;                  // this warp's query rows
    int b = blockIdx.y;
    int z = blockIdx.z;
    int i0 = blockIdx.x * TQ;
    int j_base = z * (NN / SPLIT);

    const uint4* gq4 = reinterpret_cast<const uint4*>(g_q) + (size_t)b * NN * 2 + (size_t)i0 * 2;
    const uint4* gk4 = reinterpret_cast<const uint4*>(g_k) + (size_t)b * NN * 2 + (size_t)j_base * 2;
    const uint4* gv4 = reinterpret_cast<const uint4*>(g_v) + (size_t)b * NN * 8 + (size_t)j_base * 8;

    // prologue: stage Q + tile 0 (buffer 0)
    for (int t = tid; t < 256; t += THREADS)
        CP_ASYNC16(sb + SM_Q + (uint32_t)t * 16, gq4 + t);
    for (int t = tid; t < 256; t += THREADS)
        CP_ASYNC16(sb + SM_K0 + (uint32_t)t * 16, gk4 + t);
    for (int t = tid; t < 1024; t += THREADS)
        CP_ASYNC16(sb + SM_V0 + (uint32_t)t * 16, gv4 + t);
    CP_COMMIT();
    CP_WAIT(0);
    __syncthreads();

    // per-lane ldmatrix addresses for both buffers (swizzles baked in)
    uint32_t qaddr = sb + SM_Q + (uint32_t)(qr + lr + (sub & 1) * 8) * 32
                   + (uint32_t)(((sub >> 1) ^ ((lr >> 2) & 1)) << 4);
    uint32_t koff = (uint32_t)(lr + (sub >> 1) * 8) * 32
                  + (uint32_t)(((sub & 1) ^ ((lr >> 2) & 1)) << 4);
    uint32_t voff = (uint32_t)(lr + (sub & 1) * 8) * 128;
    uint32_t kb2[2] = { sb + SM_K0 + koff, sb + SM_K1 + koff };
    uint32_t vb2[2] = { sb + SM_V0 + voff, sb + SM_V1 + voff };
    int vsub = sub >> 1;

    uint32_t qa0, qa1, qa2, qa3;
    LDMATRIX_X4(qa0, qa1, qa2, qa3, qaddr);

    float o[32];
#pragma unroll
    for (int k = 0; k < 32; k++) o[k] = 0.f;
    float lsum0 = 0.f, lsum1 = 0.f;

    for (int t = 0; t < NT; t++) {
        // prefetch next tile into the other buffer
        if (t + 1 < NT) {
            uint32_t kd = (t & 1) ? SM_K0 : SM_K1;
            uint32_t vd = (t & 1) ? SM_V0 : SM_V1;
            const uint4* gk = gk4 + (t + 1) * 256;
            const uint4* gv = gv4 + (t + 1) * 1024;
            for (int u = tid; u < 256; u += THREADS)
                CP_ASYNC16(sb + kd + (uint32_t)u * 16, gk + u);
            for (int u = tid; u < 1024; u += THREADS)
                CP_ASYNC16(sb + vd + (uint32_t)u * 16, gv + u);
            CP_COMMIT();
        }
        if (t > 0) {
            if (t + 1 < NT) CP_WAIT(1); else CP_WAIT(0);
            __syncthreads();
        }

        uint32_t kbase = kb2[t & 1];
        uint32_t vbase = vb2[t & 1];
        uint32_t acc0 = 0, acc1 = 0;   // f16x2 row-sum accumulators (per tile)

#pragma unroll
        for (int jt = 0; jt < 8; jt++) {           // 16 keys per step
            uint32_t kr0, kr1, kr2, kr3;
            LDMATRIX_X4(kr0, kr1, kr2, kr3, kbase + (uint32_t)jt * 512);

            // S = q'.k in fp16 (C-fragment == A-fragment k-slots)
            uint32_t s01a, s01b, s89a, s89b;
            MMA_16816_S_F16(s01a, s01b, qa0, qa1, qa2, qa3, kr0, kr1);  // keys 0-7
            MMA_16816_S_F16(s89a, s89b, qa0, qa1, qa2, qa3, kr2, kr3);  // keys 8-15

            // P = 2^S directly on the fragments
            uint32_t pa0, pa1, pa2, pa3;
            EX2_F16X2(pa0, s01a);   // row r,   k 0-7 slot
            EX2_F16X2(pa1, s01b);   // row r+8, k 0-7 slot
            EX2_F16X2(pa2, s89a);   // row r,   k 8-15 slot
            EX2_F16X2(pa3, s89b);   // row r+8, k 8-15 slot
            uint32_t h0, h1;
            HADD2(h0, pa0, pa2); HADD2(acc0, acc0, h0);   // rows r
            HADD2(h1, pa1, pa3); HADD2(acc1, acc1, h1);   // rows r+8

            // O += P V over 64 channels
            uint32_t vrow = vbase + (uint32_t)jt * 2048;
#pragma unroll
            for (int ct = 0; ct < 8; ct += 2) {
                uint32_t vr0, vr1, vr2, vr3;
                uint32_t va = vrow + (uint32_t)(((ct + vsub) ^ lr) << 4);
                LDMATRIX_X4_T(vr0, vr1, vr2, vr3, va);
                MMA_16816_F16(o[ct * 4 + 0], o[ct * 4 + 1], o[ct * 4 + 2], o[ct * 4 + 3],
                              pa0, pa1, pa2, pa3, vr0, vr1);
                MMA_16816_F16(o[ct * 4 + 4], o[ct * 4 + 5], o[ct * 4 + 6], o[ct * 4 + 7],
                              pa0, pa1, pa2, pa3, vr2, vr3);
            }
        }

        // flush f16x2 tile sums into f32 (tile sums ~1e2-1e3, far from f16 max)
        {
            float2 f0 = __half22float2(*reinterpret_cast<__half2*>(&acc0));
            float2 f1 = __half22float2(*reinterpret_cast<__half2*>(&acc1));
            lsum0 += f0.x + f0.y;
            lsum1 += f1.x + f1.y;
        }
        __syncthreads();   // all warps done with buffer t before its refill
    }

    // quad reduce row sums (lanes sharing a row)
    lsum0 += __shfl_xor_sync(0xffffffffu, lsum0, 1);
    lsum0 += __shfl_xor_sync(0xffffffffu, lsum0, 2);
    lsum1 += __shfl_xor_sync(0xffffffffu, lsum1, 1);
    lsum1 += __shfl_xor_sync(0xffffffffu, lsum1, 2);

    // write l partials
    float* lp = g_l[z] + (size_t)b * NN + i0;
    if ((l & 3) == 0) {
        lp[qr + (l >> 2)]     = lsum0;
        lp[qr + (l >> 2) + 8] = lsum1;
    }

    // stage O into smem as [c][i] then coalesced fp16 writes of the partial
    float* so = reinterpret_cast<float*>(smem);
    int row0 = qr + (l >> 2);
    int cb = (l & 3) * 2;
#pragma unroll
    for (int ct = 0; ct < 8; ct++) {
        int c0 = ct * 8 + cb;
        so[c0 * 128 + row0]           = o[ct * 4 + 0];
        so[(c0 + 1) * 128 + row0]     = o[ct * 4 + 1];
        so[c0 * 128 + row0 + 8]       = o[ct * 4 + 2];
        so[(c0 + 1) * 128 + row0 + 8] = o[ct * 4 + 3];
    }
    __syncthreads();

    __half* gO = g_O[z] + (size_t)b * NC * NN + i0;
    const float4* so4 = reinterpret_cast<const float4*>(so);
    for (int t = tid; t < 2048; t += THREADS) {
        int c = t >> 5;
        int i = (t & 31) * 4;
        float4 v = so4[t];
        __half2 h0 = __floats2half2_rn(v.x, v.y);
        __half2 h1 = __floats2half2_rn(v.z, v.w);
        uint2 pk = make_uint2(*reinterpret_cast<uint32_t*>(&h0),
                              *reinterpret_cast<uint32_t*>(&h1));
        *reinterpret_cast<uint2*>(gO + (size_t)c * NN + i) = pk;
    }
}

// ============================================================================
// Kernel 3: combine split-K partials: out = gamma*(O0+O1)/(l0+l1) + x
// ============================================================================
__global__ __launch_bounds__(256) void combine_kernel(
    const float* __restrict__ x,
    const float* __restrict__ gamma,
    float* __restrict__ out) {
    int t = blockIdx.x * 256 + threadIdx.x;          // 512K threads, float4 each
    int b = t >> 16;
    int rem = t & 65535;
    int c = rem >> 10;
    int i = (rem & 1023) << 2;
    size_t oidx = ((size_t)b * NC + c) * NN + i;
    size_t lidx = (size_t)b * NN + i;

    const __half2* p0 = reinterpret_cast<const __half2*>(&g_O[0][oidx]);
    const __half2* p1 = reinterpret_cast<const __half2*>(&g_O[1][oidx]);
    float2 a0 = __half22float2(p0[0]), a1 = __half22float2(p0[1]);
    float2 b0 = __half22float2(p1[0]), b1 = __half22float2(p1[1]);
    float4 l0 = *reinterpret_cast<const float4*>(&g_l[0][lidx]);
    float4 l1 = *reinterpret_cast<const float4*>(&g_l[1][lidx]);
    float4 xr = *reinterpret_cast<const float4*>(&x[oidx]);
    float g = __ldg(gamma);

    float4 r;
    r.x = g * (a0.x + b0.x) / (l0.x + l1.x) + xr.x;
    r.y = g * (a0.y + b0.y) / (l0.y + l1.y) + xr.y;
    r.z = g * (a1.x + b1.x) / (l0.z + l1.z) + xr.z;
    r.w = g * (a1.y + b1.y) / (l0.w + l1.w) + xr.w;
    *reinterpret_cast<float4*>(&out[oidx]) = r;
}

extern "C" void kernel_launch(void* const* d_in, const int* in_sizes, int n_in,
                              void* d_out, int out_size) {
    const float* x     = (const float*)d_in[0];
    const float* wq    = (const float*)d_in[1];
    const float* bq    = (const float*)d_in[2];
    const float* wk    = (const float*)d_in[3];
    const float* bk    = (const float*)d_in[4];
    const float* wv    = (const float*)d_in[5];
    const float* bv    = (const float*)d_in[6];
    const float* gamma = (const float*)d_in[7];
    float* out = (float*)d_out;

    proj_kernel<<<NB * NN / 64, 64>>>(x, wq, bq, wk, bk, wv, bv);
    attn_kernel<<<dim3(NN / TQ, NB, SPLIT), THREADS>>>();
    combine_kernel<<<NB * NC * NN / 4 / 256, 256>>>(x, gamma, out);
}

// round 7
// speedup vs baseline: 1.0891x; 1.0129x over previous
#include <cuda_runtime.h>
#include <cuda_fp16.h>
#include <cstdint>

// Problem constants
#define NB 8      // batch
#define NC 64     // channels
#define NN 4096   // H*W
#define ND 8      // qk head dim (exact, no padding: m16n8k8)
#define TQ 128    // queries per CTA
#define TK 128    // keys per tile
#define THREADS 256
#define SPLIT 2
#define NT (NN / TK / SPLIT)   // 16 key tiles per CTA

#define LOG2E 1.4426950408889634f

// Scratch (__device__ globals; no allocation allowed)
// g_q/g_k: [B, N, 8] fp16 (16B rows, no swizzle needed: 8 rows = 128B span)
//          q is pre-scaled by log2(e) so softmax uses ex2 directly.
// g_v:     [B, N, 64] fp16, c-index XOR-swizzled by (n&7)*8 (128B rows)
__device__ __align__(16) __half g_q[NB * NN * ND];
__device__ __align__(16) __half g_k[NB * NN * ND];
__device__ __align__(16) __half g_v[NB * NN * NC];
// split-K partials (fp16 O: errors damped ~1000x by the +x residual)
__device__ __align__(16) __half g_O[SPLIT][NB * NC * NN];
__device__ __align__(16) float  g_l[SPLIT][NB * NN];

// ---------------------------------------------------------------------------
// Inline PTX (sm_80-baseline: ldmatrix + mma.sync + cp.async — no tcgen05)
// ---------------------------------------------------------------------------
__device__ __forceinline__ uint32_t smem_u32(const void* p) {
    uint32_t a;
    asm("{ .reg .u64 t; cvta.to.shared.u64 t, %1; cvt.u32.u64 %0, t; }"
        : "=r"(a) : "l"(p));
    return a;
}

#define LDMATRIX_X2(r0, r1, addr) \
    asm volatile("ldmatrix.sync.aligned.m8n8.x2.shared.b16 {%0,%1}, [%2];" \
                 : "=r"(r0), "=r"(r1) : "r"(addr))

#define LDMATRIX_X4_T(r0, r1, r2, r3, addr) \
    asm volatile("ldmatrix.sync.aligned.m8n8.x4.trans.shared.b16 {%0,%1,%2,%3}, [%4];" \
                 : "=r"(r0), "=r"(r1), "=r"(r2), "=r"(r3) : "r"(addr))

// S = q.k, K=8, f16 accum; C-fragment == PV A-fragment k-slots (FA2 reuse)
#define MMA_K8_S_F16(d0, d1, a0, a1, b0) \
    asm volatile("mma.sync.aligned.m16n8k8.row.col.f16.f16.f16.f16 " \
                 "{%0,%1}, {%2,%3}, {%4}, {%5,%6};" \
                 : "=r"(d0), "=r"(d1) \
                 : "r"(a0), "r"(a1), "r"(b0), "r"(0u), "r"(0u))

// PV MMA, f16 accumulate in-place (2x rate vs f32 accum)
#define MMA_16816_PV_F16(d0, d1, a0, a1, a2, a3, b0, b1) \
    asm volatile("mma.sync.aligned.m16n8k16.row.col.f16.f16.f16.f16 " \
                 "{%0,%1}, {%2,%3,%4,%5}, {%6,%7}, {%0,%1};" \
                 : "+r"(d0), "+r"(d1) \
                 : "r"(a0), "r"(a1), "r"(a2), "r"(a3), "r"(b0), "r"(b1))

#define EX2_F16X2(d, a) \
    asm("ex2.approx.f16x2 %0, %1;" : "=r"(d) : "r"(a))
#define HADD2(d, a, b) \
    asm("add.rn.f16x2 %0, %1, %2;" : "=r"(d) : "r"(a), "r"(b))

#define CP_ASYNC16(smem_addr, gptr) \
    asm volatile("cp.async.cg.shared.global [%0], [%1], 16;" \
                 :: "r"(smem_addr), "l"(gptr) : "memory")
#define CP_COMMIT() asm volatile("cp.async.commit_group;" ::: "memory")
#define CP_WAIT(n)  asm volatile("cp.async.wait_group %0;" :: "n"(n) : "memory")

// SMEM layout (static, double-buffered K/V). Q/K rows are 16B now.
#define SM_Q   0                    // 128 x 16B  (2KB)
#define SM_K0  2048
#define SM_K1  4096
#define SM_V0  6144                 // 128 x 128B (16KB)
#define SM_V1  22528
#define SM_BYTES 38912              // epilogue reuses [0,32KB) as O stage

// ============================================================================
// Kernel 1: 1x1-conv projections, 4-way output split for occupancy.
//   Thread = (position, quarter): quarter qt computes q[2qt:2qt+2],
//   k[2qt:2qt+2], v[16qt:16qt+16]. 131072 threads (~27 warps/SM).
// ============================================================================
__global__ __launch_bounds__(64) void proj_kernel(
    const float* __restrict__ x,
    const float* __restrict__ wq, const float* __restrict__ bq,
    const float* __restrict__ wk, const float* __restrict__ bk,
    const float* __restrict__ wv, const float* __restrict__ bv) {
    __shared__ float s_wv[16 * NC], s_wq[2 * NC], s_wk[2 * NC];
    __shared__ float s_bv[16], s_bq2[2], s_bk2[2];

    int tid = threadIdx.x;
    int qt = blockIdx.y;                 // quarter 0..3

    for (int i = tid; i < 16 * NC; i += 64) s_wv[i] = wv[qt * 16 * NC + i];
    for (int i = tid; i < 2 * NC; i += 64) {
        s_wq[i] = wq[qt * 2 * NC + i];
        s_wk[i] = wk[qt * 2 * NC + i];
    }
    if (tid < 16) s_bv[tid] = bv[qt * 16 + tid];
    if (tid < 2) { s_bq2[tid] = bq[qt * 2 + tid]; s_bk2[tid] = bk[qt * 2 + tid]; }
    __syncthreads();

    int idx = blockIdx.x * 64 + tid;     // b*NN + n
    int n = idx & (NN - 1);
    int b = idx >> 12;

    const float* xp = x + (size_t)b * NC * NN + n;
    float4 xc[16];
#pragma unroll
    for (int c4 = 0; c4 < 16; c4++) {
        xc[c4].x = xp[(size_t)(4 * c4 + 0) * NN];
        xc[c4].y = xp[(size_t)(4 * c4 + 1) * NN];
        xc[c4].z = xp[(size_t)(4 * c4 + 2) * NN];
        xc[c4].w = xp[(size_t)(4 * c4 + 3) * NN];
    }

    __half* qo = g_q + (size_t)idx * ND;
    __half* ko = g_k + (size_t)idx * ND;
    __half* vo = g_v + (size_t)idx * NC;
    int swv = (n & 7) << 3;              // c-swizzle (multiple of 8: pairs survive)

    // q/k: 4 chains (2 q + 2 k outputs)
    {
        float aq0 = s_bq2[0], aq1 = s_bq2[1];
        float ak0 = s_bk2[0], ak1 = s_bk2[1];
        const float4* w0 = reinterpret_cast<const float4*>(s_wq);
        const float4* w1 = reinterpret_cast<const float4*>(s_wq + NC);
        const float4* u0 = reinterpret_cast<const float4*>(s_wk);
        const float4* u1 = reinterpret_cast<const float4*>(s_wk + NC);
#pragma unroll
        for (int c4 = 0; c4 < 16; c4++) {
            float4 xv = xc[c4];
            float4 a;
            a = w0[c4]; aq0 += a.x * xv.x + a.y * xv.y + a.z * xv.z + a.w * xv.w;
            a = w1[c4]; aq1 += a.x * xv.x + a.y * xv.y + a.z * xv.z + a.w * xv.w;
            a = u0[c4]; ak0 += a.x * xv.x + a.y * xv.y + a.z * xv.z + a.w * xv.w;
            a = u1[c4]; ak1 += a.x * xv.x + a.y * xv.y + a.z * xv.z + a.w * xv.w;
        }
        *reinterpret_cast<__half2*>(qo + 2 * qt) =
            __floats2half2_rn(aq0 * LOG2E, aq1 * LOG2E);
        *reinterpret_cast<__half2*>(ko + 2 * qt) = __floats2half2_rn(ak0, ak1);
    }

    // v: 4 groups of 4 chains
#pragma unroll
    for (int g = 0; g < 4; g++) {
        int o = 16 * qt + 4 * g;
        float a0 = s_bv[4 * g], a1 = s_bv[4 * g + 1];
        float a2 = s_bv[4 * g + 2], a3 = s_bv[4 * g + 3];
        const float4* w0 = reinterpret_cast<const float4*>(s_wv + (4 * g) * NC);
        const float4* w1 = reinterpret_cast<const float4*>(s_wv + (4 * g + 1) * NC);
        const float4* w2 = reinterpret_cast<const float4*>(s_wv + (4 * g + 2) * NC);
        const float4* w3 = reinterpret_cast<const float4*>(s_wv + (4 * g + 3) * NC);
#pragma unroll
        for (int c4 = 0; c4 < 16; c4++) {
            float4 xv = xc[c4];
            float4 a;
            a = w0[c4]; a0 += a.x * xv.x + a.y * xv.y + a.z * xv.z + a.w * xv.w;
            a = w1[c4]; a1 += a.x * xv.x + a.y * xv.y + a.z * xv.z + a.w * xv.w;
            a = w2[c4]; a2 += a.x * xv.x + a.y * xv.y + a.z * xv.z + a.w * xv.w;
            a = w3[c4]; a3 += a.x * xv.x + a.y * xv.y + a.z * xv.z + a.w * xv.w;
        }
        *reinterpret_cast<__half2*>(vo + (o ^ swv))       = __floats2half2_rn(a0, a1);
        *reinterpret_cast<__half2*>(vo + ((o + 2) ^ swv)) = __floats2half2_rn(a2, a3);
    }
}

// ============================================================================
// Kernel 2: flash attention partial (split-K), fp16 HMMA.
//   K=8 S-MMA (no padding), ex2 on fragments, PV f16-accum flushed to fp32
//   per 128-key tile.
// ============================================================================
__global__ __launch_bounds__(THREADS, 3) void attn_kernel() {
    __shared__ __align__(16) char smem[SM_BYTES];
    uint32_t sb = smem_u32(smem);

    int tid = threadIdx.x;
    int w = tid >> 5, l = tid & 31;
    int lr = l & 7, sub = l >> 3;
    int qr = w * 16;
    int b = blockIdx.y;
    int z = blockIdx.z;
    int i0 = blockIdx.x * TQ;
    int j_base = z * (NN / SPLIT);

    const uint4* gq4 = reinterpret_cast<const uint4*>(g_q) + (size_t)b * NN + i0;
    const uint4* gk4 = reinterpret_cast<const uint4*>(g_k) + (size_t)b * NN + j_base;
    const uint4* gv4 = reinterpret_cast<const uint4*>(g_v) + (size_t)b * NN * 8 + (size_t)j_base * 8;

    // prologue: stage Q + tile 0 (buffer 0)
    for (int t = tid; t < 128; t += THREADS)
        CP_ASYNC16(sb + SM_Q + (uint32_t)t * 16, gq4 + t);
    for (int t = tid; t < 128; t += THREADS)
        CP_ASYNC16(sb + SM_K0 + (uint32_t)t * 16, gk4 + t);
    for (int t = tid; t < 1024; t += THREADS)
        CP_ASYNC16(sb + SM_V0 + (uint32_t)t * 16, gv4 + t);
    CP_COMMIT();
    CP_WAIT(0);
    __syncthreads();

    // ldmatrix addresses: Q/K rows are 16B, 16 rows per x2 (conflict-free)
    uint32_t qaddr = sb + SM_Q + (uint32_t)(qr + (l & 15)) * 16;
    uint32_t koff = (uint32_t)(l & 15) * 16;
    uint32_t voff = (uint32_t)(lr + (sub & 1) * 8) * 128;
    uint32_t kb2[2] = { sb + SM_K0 + koff, sb + SM_K1 + koff };
    uint32_t vb2[2] = { sb + SM_V0 + voff, sb + SM_V1 + voff };
    int vsub = sub >> 1;

    uint32_t qa0, qa1;
    LDMATRIX_X2(qa0, qa1, qaddr);

    float o[32];
#pragma unroll
    for (int k = 0; k < 32; k++) o[k] = 0.f;
    float lsum0 = 0.f, lsum1 = 0.f;

    for (int t = 0; t < NT; t++) {
        // prefetch next tile into the other buffer
        if (t + 1 < NT) {
            uint32_t kd = (t & 1) ? SM_K0 : SM_K1;
            uint32_t vd = (t & 1) ? SM_V0 : SM_V1;
            const uint4* gk = gk4 + (t + 1) * 128;
            const uint4* gv = gv4 + (t + 1) * 1024;
            for (int u = tid; u < 128; u += THREADS)
                CP_ASYNC16(sb + kd + (uint32_t)u * 16, gk + u);
            for (int u = tid; u < 1024; u += THREADS)
                CP_ASYNC16(sb + vd + (uint32_t)u * 16, gv + u);
            CP_COMMIT();
        }
        if (t > 0) {
            if (t + 1 < NT) CP_WAIT(1); else CP_WAIT(0);
            __syncthreads();
        }

        uint32_t kbase = kb2[t & 1];
        uint32_t vbase = vb2[t & 1];
        uint32_t acc0 = 0, acc1 = 0;     // f16x2 row-sum accumulators
        uint32_t o16[16];                // f16x2 PV accumulators (this tile)
#pragma unroll
        for (int k = 0; k < 16; k++) o16[k] = 0;

#pragma unroll
        for (int jt = 0; jt < 8; jt++) {           // 16 keys per step
            uint32_t kr0, kr1;
            LDMATRIX_X2(kr0, kr1, kbase + (uint32_t)jt * 256);

            // S = q'.k (K=8, f16 accum); fragments are PV A-slots directly
            uint32_t pa0, pa1, pa2, pa3;
            MMA_K8_S_F16(pa0, pa1, qa0, qa1, kr0);  // keys 0-7
            MMA_K8_S_F16(pa2, pa3, qa0, qa1, kr1);  // keys 8-15

            // P = 2^S
            EX2_F16X2(pa0, pa0);
            EX2_F16X2(pa1, pa1);
            EX2_F16X2(pa2, pa2);
            EX2_F16X2(pa3, pa3);
            uint32_t h0, h1;
            HADD2(h0, pa0, pa2); HADD2(acc0, acc0, h0);   // rows r
            HADD2(h1, pa1, pa3); HADD2(acc1, acc1, h1);   // rows r+8

            // O_tile += P V (f16 accumulate, 2x tensor rate)
            uint32_t vrow = vbase + (uint32_t)jt * 2048;
#pragma unroll
            for (int ct = 0; ct < 8; ct += 2) {
                uint32_t vr0, vr1, vr2, vr3;
                uint32_t va = vrow + (uint32_t)(((ct + vsub) ^ lr) << 4);
                LDMATRIX_X4_T(vr0, vr1, vr2, vr3, va);
                MMA_16816_PV_F16(o16[ct * 2 + 0], o16[ct * 2 + 1],
                                 pa0, pa1, pa2, pa3, vr0, vr1);
                MMA_16816_PV_F16(o16[ct * 2 + 2], o16[ct * 2 + 3],
                                 pa0, pa1, pa2, pa3, vr2, vr3);
            }
        }

        // flush tile: f16x2 -> f32 accumulators
#pragma unroll
        for (int ct = 0; ct < 8; ct++) {
            float2 f0 = __half22float2(*reinterpret_cast<__half2*>(&o16[ct * 2]));
            float2 f1 = __half22float2(*reinterpret_cast<__half2*>(&o16[ct * 2 + 1]));
            o[ct * 4 + 0] += f0.x;
            o[ct * 4 + 1] += f0.y;
            o[ct * 4 + 2] += f1.x;
            o[ct * 4 + 3] += f1.y;
        }
        {
            float2 f0 = __half22float2(*reinterpret_cast<__half2*>(&acc0));
            float2 f1 = __half22float2(*reinterpret_cast<__half2*>(&acc1));
            lsum0 += f0.x + f0.y;
            lsum1 += f1.x + f1.y;
        }
        __syncthreads();   // all warps done with buffer t before its refill
    }

    // quad reduce row sums
    lsum0 += __shfl_xor_sync(0xffffffffu, lsum0, 1);
    lsum0 += __shfl_xor_sync(0xffffffffu, lsum0, 2);
    lsum1 += __shfl_xor_sync(0xffffffffu, lsum1, 1);
    lsum1 += __shfl_xor_sync(0xffffffffu, lsum1, 2);

    float* lp = g_l[z] + (size_t)b * NN + i0;
    if ((l & 3) == 0) {
        lp[qr + (l >> 2)]     = lsum0;
        lp[qr + (l >> 2) + 8] = lsum1;
    }

    // stage O into smem as [c][i] then coalesced fp16 writes of the partial
    float* so = reinterpret_cast<float*>(smem);
    int row0 = qr + (l >> 2);
    int cb = (l & 3) * 2;
#pragma unroll
    for (int ct = 0; ct < 8; ct++) {
        int c0 = ct * 8 + cb;
        so[c0 * 128 + row0]           = o[ct * 4 + 0];
        so[(c0 + 1) * 128 + row0]     = o[ct * 4 + 1];
        so[c0 * 128 + row0 + 8]       = o[ct * 4 + 2];
        so[(c0 + 1) * 128 + row0 + 8] = o[ct * 4 + 3];
    }
    __syncthreads();

    __half* gO = g_O[z] + (size_t)b * NC * NN + i0;
    const float4* so4 = reinterpret_cast<const float4*>(so);
    for (int t = tid; t < 2048; t += THREADS) {
        int c = t >> 5;
        int i = (t & 31) * 4;
        float4 v = so4[t];
        __half2 h0 = __floats2half2_rn(v.x, v.y);
        __half2 h1 = __floats2half2_rn(v.z, v.w);
        uint2 pk = make_uint2(*reinterpret_cast<uint32_t*>(&h0),
                              *reinterpret_cast<uint32_t*>(&h1));
        *reinterpret_cast<uint2*>(gO + (size_t)c * NN + i) = pk;
    }
}

// ============================================================================
// Kernel 3: combine split-K partials: out = gamma*(O0+O1)/(l0+l1) + x
// ============================================================================
__global__ __launch_bounds__(256) void combine_kernel(
    const float* __restrict__ x,
    const float* __restrict__ gamma,
    float* __restrict__ out) {
    int t = blockIdx.x * 256 + threadIdx.x;
    int b = t >> 16;
    int rem = t & 65535;
    int c = rem >> 10;
    int i = (rem & 1023) << 2;
    size_t oidx = ((size_t)b * NC + c) * NN + i;
    size_t lidx = (size_t)b * NN + i;

    const __half2* p0 = reinterpret_cast<const __half2*>(&g_O[0][oidx]);
    const __half2* p1 = reinterpret_cast<const __half2*>(&g_O[1][oidx]);
    float2 a0 = __half22float2(p0[0]), a1 = __half22float2(p0[1]);
    float2 b0 = __half22float2(p1[0]), b1 = __half22float2(p1[1]);
    float4 l0 = *reinterpret_cast<const float4*>(&g_l[0][lidx]);
    float4 l1 = *reinterpret_cast<const float4*>(&g_l[1][lidx]);
    float4 xr = *reinterpret_cast<const float4*>(&x[oidx]);
    float g = __ldg(gamma);

    float4 r;
    r.x = g * (a0.x + b0.x) / (l0.x + l1.x) + xr.x;
    r.y = g * (a0.y + b0.y) / (l0.y + l1.y) + xr.y;
    r.z = g * (a1.x + b1.x) / (l0.z + l1.z) + xr.z;
    r.w = g * (a1.y + b1.y) / (l0.w + l1.w) + xr.w;
    *reinterpret_cast<float4*>(&out[oidx]) = r;
}

extern "C" void kernel_launch(void* const* d_in, const int* in_sizes, int n_in,
                              void* d_out, int out_size) {
    const float* x     = (const float*)d_in[0];
    const float* wq    = (const float*)d_in[1];
    const float* bq    = (const float*)d_in[2];
    const float* wk    = (const float*)d_in[3];
    const float* bk    = (const float*)d_in[4];
    const float* wv    = (const float*)d_in[5];
    const float* bv    = (const float*)d_in[6];
    const float* gamma = (const float*)d_in[7];
    float* out = (float*)d_out;

    proj_kernel<<<dim3(NB * NN / 64, 4), 64>>>(x, wq, bq, wk, bk, wv, bv);
    attn_kernel<<<dim3(NN / TQ, NB, SPLIT), THREADS>>>();
    combine_kernel<<<NB * NC * NN / 4 / 256, 256>>>(x, gamma, out);
}

// round 8
// speedup vs baseline: 1.1609x; 1.0659x over previous
#include <cuda_runtime.h>
#include <cuda_fp16.h>
#include <cstdint>

// Problem constants
#define NB 8      // batch
#define NC 64     // channels
#define NN 4096   // H*W
#define ND 8      // qk head dim (exact, no padding: m16n8k8)
#define TQ 64     // queries per CTA (4 warps x 16 rows)
#define TK 128    // keys per tile
#define THREADS 128
#define NT (NN / TK)           // 32 key tiles per CTA (no split)

#define LOG2E 1.4426950408889634f

// Scratch (__device__ globals; no allocation allowed)
// g_q/g_k: [B, N, 8] fp16 (16B rows). q pre-scaled by log2(e).
// g_v:     [B, N, 64] fp16, c-index XOR-swizzled by (n&7)*8 (128B rows)
__device__ __align__(16) __half g_q[NB * NN * ND];
__device__ __align__(16) __half g_k[NB * NN * ND];
__device__ __align__(16) __half g_v[NB * NN * NC];

// ---------------------------------------------------------------------------
// Inline PTX
// ---------------------------------------------------------------------------
__device__ __forceinline__ uint32_t smem_u32(const void* p) {
    uint32_t a;
    asm("{ .reg .u64 t; cvta.to.shared.u64 t, %1; cvt.u32.u64 %0, t; }"
        : "=r"(a) : "l"(p));
    return a;
}

// packed f32x2 FMA (works via ptxas on this toolchain; verified round 1)
__device__ __forceinline__ void fma2(unsigned long long& d,
                                     unsigned long long a,
                                     unsigned long long b) {
    asm("fma.rn.f32x2 %0, %1, %2, %0;" : "+l"(d) : "l"(a), "l"(b));
}
__device__ __forceinline__ unsigned long long pack2(float x, float y) {
    unsigned long long u;
    asm("mov.b64 %0, {%1, %2};" : "=l"(u) : "f"(x), "f"(y));
    return u;
}
__device__ __forceinline__ float2 unpack2(unsigned long long u) {
    float2 r;
    asm("mov.b64 {%0, %1}, %2;" : "=f"(r.x), "=f"(r.y) : "l"(u));
    return r;
}

#define LDMATRIX_X2(r0, r1, addr) \
    asm volatile("ldmatrix.sync.aligned.m8n8.x2.shared.b16 {%0,%1}, [%2];" \
                 : "=r"(r0), "=r"(r1) : "r"(addr))

#define LDMATRIX_X4_T(r0, r1, r2, r3, addr) \
    asm volatile("ldmatrix.sync.aligned.m8n8.x4.trans.shared.b16 {%0,%1,%2,%3}, [%4];" \
                 : "=r"(r0), "=r"(r1), "=r"(r2), "=r"(r3) : "r"(addr))

// S = q.k, K=8, f16 accum; C-fragment == PV A-fragment k-slots (FA2 reuse)
#define MMA_K8_S_F16(d0, d1, a0, a1, b0) \
    asm volatile("mma.sync.aligned.m16n8k8.row.col.f16.f16.f16.f16 " \
                 "{%0,%1}, {%2,%3}, {%4}, {%5,%6};" \
                 : "=r"(d0), "=r"(d1) \
                 : "r"(a0), "r"(a1), "r"(b0), "r"(0u), "r"(0u))

// PV MMA, f16 accumulate in-place (2x rate vs f32 accum)
#define MMA_16816_PV_F16(d0, d1, a0, a1, a2, a3, b0, b1) \
    asm volatile("mma.sync.aligned.m16n8k16.row.col.f16.f16.f16.f16 " \
                 "{%0,%1}, {%2,%3,%4,%5}, {%6,%7}, {%0,%1};" \
                 : "+r"(d0), "+r"(d1) \
                 : "r"(a0), "r"(a1), "r"(a2), "r"(a3), "r"(b0), "r"(b1))

#define EX2_F16X2(d, a) \
    asm("ex2.approx.f16x2 %0, %1;" : "=r"(d) : "r"(a))
#define HADD2(d, a, b) \
    asm("add.rn.f16x2 %0, %1, %2;" : "=r"(d) : "r"(a), "r"(b))

#define CP_ASYNC16(smem_addr, gptr) \
    asm volatile("cp.async.cg.shared.global [%0], [%1], 16;" \
                 :: "r"(smem_addr), "l"(gptr) : "memory")
#define CP_COMMIT() asm volatile("cp.async.commit_group;" ::: "memory")
#define CP_WAIT(n)  asm volatile("cp.async.wait_group %0;" :: "n"(n) : "memory")

// SMEM layout (static, double-buffered K/V)
#define SM_Q   0                    // 64 x 16B   (1KB)
#define SM_K0  1024                 // 128 x 16B  (2KB)
#define SM_K1  3072
#define SM_V0  5120                 // 128 x 128B (16KB)
#define SM_V1  21504
#define SM_BYTES 37888              // epilogue reuses [0,16KB) as O stage

// ============================================================================
// Kernel 1: 1x1-conv projections with packed f32x2 FMA (halved FMA instrs),
//   8 accumulation chains, 2-way output split (halves x re-read redundancy).
//   blockIdx.y = half h: computes q[4h:4h+4], k[4h:4h+4], v[32h:32h+32].
// ============================================================================
__global__ __launch_bounds__(64) void proj_kernel(
    const float* __restrict__ x,
    const float* __restrict__ wq, const float* __restrict__ bq,
    const float* __restrict__ wk, const float* __restrict__ bk,
    const float* __restrict__ wv, const float* __restrict__ bv) {
    __shared__ __align__(16) float s_wv[32 * NC];
    __shared__ __align__(16) float s_wq[4 * NC];
    __shared__ __align__(16) float s_wk[4 * NC];
    __shared__ float s_bv[32], s_bq4[4], s_bk4[4];

    int tid = threadIdx.x;
    int h = blockIdx.y;                  // half 0..1

    for (int i = tid; i < 32 * NC; i += 64) s_wv[i] = wv[h * 32 * NC + i];
    for (int i = tid; i < 4 * NC; i += 64) {
        s_wq[i] = wq[h * 4 * NC + i];
        s_wk[i] = wk[h * 4 * NC + i];
    }
    if (tid < 32) s_bv[tid] = bv[h * 32 + tid];
    if (tid < 4) { s_bq4[tid] = bq[h * 4 + tid]; s_bk4[tid] = bk[h * 4 + tid]; }
    __syncthreads();

    int idx = blockIdx.x * 64 + tid;     // b*NN + n
    int n = idx & (NN - 1);
    int b = idx >> 12;

    const float* xp = x + (size_t)b * NC * NN + n;
    unsigned long long x2[32];           // x column as 32 channel-pairs
#pragma unroll
    for (int j = 0; j < 32; j++)
        x2[j] = pack2(xp[(size_t)(2 * j) * NN], xp[(size_t)(2 * j + 1) * NN]);

    __half* qo = g_q + (size_t)idx * ND;
    __half* ko = g_k + (size_t)idx * ND;
    __half* vo = g_v + (size_t)idx * NC;
    int swv = (n & 7) << 3;              // c-swizzle (multiple of 8: pairs survive)

    // q/k: 2 groups of (2q + 2k) outputs, 2 interleaved partials each = 8 chains
#pragma unroll
    for (int og = 0; og < 2; og++) {
        unsigned long long aq[2][2] = {{0ull, 0ull}, {0ull, 0ull}};
        unsigned long long ak[2][2] = {{0ull, 0ull}, {0ull, 0ull}};
        const ulonglong2* wr0 = reinterpret_cast<const ulonglong2*>(s_wq + (2 * og) * NC);
        const ulonglong2* wr1 = reinterpret_cast<const ulonglong2*>(s_wq + (2 * og + 1) * NC);
        const ulonglong2* ur0 = reinterpret_cast<const ulonglong2*>(s_wk + (2 * og) * NC);
        const ulonglong2* ur1 = reinterpret_cast<const ulonglong2*>(s_wk + (2 * og + 1) * NC);
#pragma unroll
        for (int c4 = 0; c4 < 16; c4++) {
            ulonglong2 w;
            int p = c4 & 1;
            w = wr0[c4]; fma2(aq[0][p], w.x, x2[2 * c4]); fma2(aq[0][p], w.y, x2[2 * c4 + 1]);
            w = wr1[c4]; fma2(aq[1][p], w.x, x2[2 * c4]); fma2(aq[1][p], w.y, x2[2 * c4 + 1]);
            w = ur0[c4]; fma2(ak[0][p], w.x, x2[2 * c4]); fma2(ak[0][p], w.y, x2[2 * c4 + 1]);
            w = ur1[c4]; fma2(ak[1][p], w.x, x2[2 * c4]); fma2(ak[1][p], w.y, x2[2 * c4 + 1]);
        }
        float2 q0a = unpack2(aq[0][0]), q0b = unpack2(aq[0][1]);
        float2 q1a = unpack2(aq[1][0]), q1b = unpack2(aq[1][1]);
        float2 k0a = unpack2(ak[0][0]), k0b = unpack2(ak[0][1]);
        float2 k1a = unpack2(ak[1][0]), k1b = unpack2(ak[1][1]);
        float fq0 = (q0a.x + q0a.y + q0b.x + q0b.y + s_bq4[2 * og]) * LOG2E;
        float fq1 = (q1a.x + q1a.y + q1b.x + q1b.y + s_bq4[2 * og + 1]) * LOG2E;
        float fk0 = k0a.x + k0a.y + k0b.x + k0b.y + s_bk4[2 * og];
        float fk1 = k1a.x + k1a.y + k1b.x + k1b.y + s_bk4[2 * og + 1];
        *reinterpret_cast<__half2*>(qo + 4 * h + 2 * og) = __floats2half2_rn(fq0, fq1);
        *reinterpret_cast<__half2*>(ko + 4 * h + 2 * og) = __floats2half2_rn(fk0, fk1);
    }

    // v: 8 groups of 4 outputs, 2 interleaved partials each = 8 chains
    for (int g = 0; g < 8; g++) {
        int o = 32 * h + 4 * g;
        unsigned long long a0[2] = {0ull, 0ull}, a1[2] = {0ull, 0ull};
        unsigned long long a2[2] = {0ull, 0ull}, a3[2] = {0ull, 0ull};
        const ulonglong2* w0 = reinterpret_cast<const ulonglong2*>(s_wv + (4 * g) * NC);
        const ulonglong2* w1 = reinterpret_cast<const ulonglong2*>(s_wv + (4 * g + 1) * NC);
        const ulonglong2* w2 = reinterpret_cast<const ulonglong2*>(s_wv + (4 * g + 2) * NC);
        const ulonglong2* w3 = reinterpret_cast<const ulonglong2*>(s_wv + (4 * g + 3) * NC);
#pragma unroll
        for (int c4 = 0; c4 < 16; c4++) {
            ulonglong2 w;
            int p = c4 & 1;
            w = w0[c4]; fma2(a0[p], w.x, x2[2 * c4]); fma2(a0[p], w.y, x2[2 * c4 + 1]);
            w = w1[c4]; fma2(a1[p], w.x, x2[2 * c4]); fma2(a1[p], w.y, x2[2 * c4 + 1]);
            w = w2[c4]; fma2(a2[p], w.x, x2[2 * c4]); fma2(a2[p], w.y, x2[2 * c4 + 1]);
            w = w3[c4]; fma2(a3[p], w.x, x2[2 * c4]); fma2(a3[p], w.y, x2[2 * c4 + 1]);
        }
        float2 f0a = unpack2(a0[0]), f0b = unpack2(a0[1]);
        float2 f1a = unpack2(a1[0]), f1b = unpack2(a1[1]);
        float2 f2a = unpack2(a2[0]), f2b = unpack2(a2[1]);
        float2 f3a = unpack2(a3[0]), f3b = unpack2(a3[1]);
        float r0 = f0a.x + f0a.y + f0b.x + f0b.y + s_bv[4 * g];
        float r1 = f1a.x + f1a.y + f1b.x + f1b.y + s_bv[4 * g + 1];
        float r2 = f2a.x + f2a.y + f2b.x + f2b.y + s_bv[4 * g + 2];
        float r3 = f3a.x + f3a.y + f3b.x + f3b.y + s_bv[4 * g + 3];
        *reinterpret_cast<__half2*>(vo + (o ^ swv))       = __floats2half2_rn(r0, r1);
        *reinterpret_cast<__half2*>(vo + ((o + 2) ^ swv)) = __floats2half2_rn(r2, r3);
    }
}

// ============================================================================
// Kernel 2: flash attention, no split-K. 512 CTAs (TQ=64, 4 warps), one wave.
//   K=8 S-MMA, ex2 on fragments, PV f16-accum flushed to fp32 per tile.
//   Epilogue applies gamma/l + residual and writes final output directly.
// ============================================================================
__global__ __launch_bounds__(THREADS, 6) void attn_kernel(
    const float* __restrict__ x,
    const float* __restrict__ gamma,
    float* __restrict__ out) {
    __shared__ __align__(16) char smem[SM_BYTES];
    uint32_t sb = smem_u32(smem);

    int tid = threadIdx.x;
    int w = tid >> 5, l = tid & 31;
    int lr = l & 7, sub = l >> 3;
    int qr = w * 16;                   // warp's query rows within 64
    int b = blockIdx.y;
    int i0 = blockIdx.x * TQ;

    const uint4* gq4 = reinterpret_cast<const uint4*>(g_q) + (size_t)b * NN + i0;
    const uint4* gk4 = reinterpret_cast<const uint4*>(g_k) + (size_t)b * NN;
    const uint4* gv4 = reinterpret_cast<const uint4*>(g_v) + (size_t)b * NN * 8;

    // prologue: stage Q + tile 0 (buffer 0)
    for (int t = tid; t < 64; t += THREADS)
        CP_ASYNC16(sb + SM_Q + (uint32_t)t * 16, gq4 + t);
    for (int t = tid; t < 128; t += THREADS)
        CP_ASYNC16(sb + SM_K0 + (uint32_t)t * 16, gk4 + t);
    for (int t = tid; t < 1024; t += THREADS)
        CP_ASYNC16(sb + SM_V0 + (uint32_t)t * 16, gv4 + t);
    CP_COMMIT();
    CP_WAIT(0);
    __syncthreads();

    uint32_t qaddr = sb + SM_Q + (uint32_t)(qr + (l & 15)) * 16;
    uint32_t koff = (uint32_t)(l & 15) * 16;
    uint32_t voff = (uint32_t)(lr + (sub & 1) * 8) * 128;
    uint32_t kb2[2] = { sb + SM_K0 + koff, sb + SM_K1 + koff };
    uint32_t vb2[2] = { sb + SM_V0 + voff, sb + SM_V1 + voff };
    int vsub = sub >> 1;

    uint32_t qa0, qa1;
    LDMATRIX_X2(qa0, qa1, qaddr);

    float o[32];
#pragma unroll
    for (int k = 0; k < 32; k++) o[k] = 0.f;
    float lsum0 = 0.f, lsum1 = 0.f;

    for (int t = 0; t < NT; t++) {
        if (t + 1 < NT) {
            uint32_t kd = (t & 1) ? SM_K0 : SM_K1;
            uint32_t vd = (t & 1) ? SM_V0 : SM_V1;
            const uint4* gk = gk4 + (t + 1) * 128;
            const uint4* gv = gv4 + (t + 1) * 1024;
            for (int u = tid; u < 128; u += THREADS)
                CP_ASYNC16(sb + kd + (uint32_t)u * 16, gk + u);
            for (int u = tid; u < 1024; u += THREADS)
                CP_ASYNC16(sb + vd + (uint32_t)u * 16, gv + u);
            CP_COMMIT();
        }
        if (t > 0) {
            if (t + 1 < NT) CP_WAIT(1); else CP_WAIT(0);
            __syncthreads();
        }

        uint32_t kbase = kb2[t & 1];
        uint32_t vbase = vb2[t & 1];
        uint32_t acc0 = 0, acc1 = 0;
        uint32_t o16[16];
#pragma unroll
        for (int k = 0; k < 16; k++) o16[k] = 0;

#pragma unroll
        for (int jt = 0; jt < 8; jt++) {           // 16 keys per step
            uint32_t kr0, kr1;
            LDMATRIX_X2(kr0, kr1, kbase + (uint32_t)jt * 256);

            uint32_t pa0, pa1, pa2, pa3;
            MMA_K8_S_F16(pa0, pa1, qa0, qa1, kr0);
            MMA_K8_S_F16(pa2, pa3, qa0, qa1, kr1);

            EX2_F16X2(pa0, pa0);
            EX2_F16X2(pa1, pa1);
            EX2_F16X2(pa2, pa2);
            EX2_F16X2(pa3, pa3);
            uint32_t h0, h1;
            HADD2(h0, pa0, pa2); HADD2(acc0, acc0, h0);
            HADD2(h1, pa1, pa3); HADD2(acc1, acc1, h1);

            uint32_t vrow = vbase + (uint32_t)jt * 2048;
#pragma unroll
            for (int ct = 0; ct < 8; ct += 2) {
                uint32_t vr0, vr1, vr2, vr3;
                uint32_t va = vrow + (uint32_t)(((ct + vsub) ^ lr) << 4);
                LDMATRIX_X4_T(vr0, vr1, vr2, vr3, va);
                MMA_16816_PV_F16(o16[ct * 2 + 0], o16[ct * 2 + 1],
                                 pa0, pa1, pa2, pa3, vr0, vr1);
                MMA_16816_PV_F16(o16[ct * 2 + 2], o16[ct * 2 + 3],
                                 pa0, pa1, pa2, pa3, vr2, vr3);
            }
        }

        // flush tile: f16x2 -> f32 accumulators
#pragma unroll
        for (int ct = 0; ct < 8; ct++) {
            float2 f0 = __half22float2(*reinterpret_cast<__half2*>(&o16[ct * 2]));
            float2 f1 = __half22float2(*reinterpret_cast<__half2*>(&o16[ct * 2 + 1]));
            o[ct * 4 + 0] += f0.x;
            o[ct * 4 + 1] += f0.y;
            o[ct * 4 + 2] += f1.x;
            o[ct * 4 + 3] += f1.y;
        }
        {
            float2 f0 = __half22float2(*reinterpret_cast<__half2*>(&acc0));
            float2 f1 = __half22float2(*reinterpret_cast<__half2*>(&acc1));
            lsum0 += f0.x + f0.y;
            lsum1 += f1.x + f1.y;
        }
        __syncthreads();
    }

    // quad reduce row sums
    lsum0 += __shfl_xor_sync(0xffffffffu, lsum0, 1);
    lsum0 += __shfl_xor_sync(0xffffffffu, lsum0, 2);
    lsum1 += __shfl_xor_sync(0xffffffffu, lsum1, 1);
    lsum1 += __shfl_xor_sync(0xffffffffu, lsum1, 2);
    float g = __ldg(gamma);
    float sc0 = g / lsum0, sc1 = g / lsum1;

    // epilogue: stage scaled O as [c][i] (64x64 f32 = 16KB), then residual write
    __syncthreads();                   // all warps done with K/V smem
    float* so = reinterpret_cast<float*>(smem);
    int row0 = qr + (l >> 2);
    int cb = (l & 3) * 2;
#pragma unroll
    for (int ct = 0; ct < 8; ct++) {
        int c0 = ct * 8 + cb;
        so[c0 * 64 + row0]          = o[ct * 4 + 0] * sc0;
        so[(c0 + 1) * 64 + row0]    = o[ct * 4 + 1] * sc0;
        so[c0 * 64 + row0 + 8]      = o[ct * 4 + 2] * sc1;
        so[(c0 + 1) * 64 + row0 + 8] = o[ct * 4 + 3] * sc1;
    }
    __syncthreads();

    size_t base = (size_t)b * NC * NN + (size_t)i0;
    const float4* so4 = reinterpret_cast<const float4*>(so);
    for (int t = tid; t < 1024; t += THREADS) {
        int c = t >> 4;
        int i = (t & 15) * 4;
        size_t idx = base + (size_t)c * NN + i;
        float4 v = so4[t];
        float4 xr = *reinterpret_cast<const float4*>(x + idx);
        v.x += xr.x; v.y += xr.y; v.z += xr.z; v.w += xr.w;
        *reinterpret_cast<float4*>(out + idx) = v;
    }
}

extern "C" void kernel_launch(void* const* d_in, const int* in_sizes, int n_in,
                              void* d_out, int out_size) {
    const float* x     = (const float*)d_in[0];
    const float* wq    = (const float*)d_in[1];
    const float* bq    = (const float*)d_in[2];
    const float* wk    = (const float*)d_in[3];
    const float* bk    = (const float*)d_in[4];
    const float* wv    = (const float*)d_in[5];
    const float* bv    = (const float*)d_in[6];
    const float* gamma = (const float*)d_in[7];
    float* out = (float*)d_out;

    proj_kernel<<<dim3(NB * NN / 64, 2), 64>>>(x, wq, bq, wk, bk, wv, bv);
    attn_kernel<<<dim3(NN / TQ, NB), THREADS>>>(x, gamma, out);
}

// round 9
// speedup vs baseline: 1.2779x; 1.1008x over previous
#include <cuda_runtime.h>
#include <cuda_fp16.h>
#include <cstdint>

// Problem constants
#define NB 8      // batch
#define NC 64     // channels
#define NN 4096   // H*W
#define ND 8      // qk head dim (exact, no padding: m16n8k8)
#define TQ 64     // queries per CTA (4 warps x 16 rows)
#define TK 128    // keys per tile
#define THREADS 128
#define SPLIT 2
#define NT (NN / TK / SPLIT)   // 16 key tiles per CTA

#define LOG2E 1.4426950408889634f

// Scratch (__device__ globals; no allocation allowed)
// g_q/g_k: [B, N, 8] fp16 (16B rows). q pre-scaled by log2(e).
// g_v:     [B, N, 64] fp16, c-index XOR-swizzled by (n&7)*8 (128B rows)
__device__ __align__(16) __half g_q[NB * NN * ND];
__device__ __align__(16) __half g_k[NB * NN * ND];
__device__ __align__(16) __half g_v[NB * NN * NC];
// split-K partials (fp16 O: errors damped ~1000x by the +x residual)
__device__ __align__(16) __half g_O[SPLIT][NB * NC * NN];
__device__ __align__(16) float  g_l[SPLIT][NB * NN];

// ---------------------------------------------------------------------------
// Inline PTX
// ---------------------------------------------------------------------------
__device__ __forceinline__ uint32_t smem_u32(const void* p) {
    uint32_t a;
    asm("{ .reg .u64 t; cvta.to.shared.u64 t, %1; cvt.u32.u64 %0, t; }"
        : "=r"(a) : "l"(p));
    return a;
}

// packed f32x2 FMA
__device__ __forceinline__ void fma2(unsigned long long& d,
                                     unsigned long long a,
                                     unsigned long long b) {
    asm("fma.rn.f32x2 %0, %1, %2, %0;" : "+l"(d) : "l"(a), "l"(b));
}
__device__ __forceinline__ unsigned long long pack2(float x, float y) {
    unsigned long long u;
    asm("mov.b64 %0, {%1, %2};" : "=l"(u) : "f"(x), "f"(y));
    return u;
}
__device__ __forceinline__ float2 unpack2(unsigned long long u) {
    float2 r;
    asm("mov.b64 {%0, %1}, %2;" : "=f"(r.x), "=f"(r.y) : "l"(u));
    return r;
}

#define LDMATRIX_X2(r0, r1, addr) \
    asm volatile("ldmatrix.sync.aligned.m8n8.x2.shared.b16 {%0,%1}, [%2];" \
                 : "=r"(r0), "=r"(r1) : "r"(addr))

#define LDMATRIX_X4_T(r0, r1, r2, r3, addr) \
    asm volatile("ldmatrix.sync.aligned.m8n8.x4.trans.shared.b16 {%0,%1,%2,%3}, [%4];" \
                 : "=r"(r0), "=r"(r1), "=r"(r2), "=r"(r3) : "r"(addr))

// S = q.k, K=8, f16 accum; C-fragment == PV A-fragment k-slots (FA2 reuse)
#define MMA_K8_S_F16(d0, d1, a0, a1, b0) \
    asm volatile("mma.sync.aligned.m16n8k8.row.col.f16.f16.f16.f16 " \
                 "{%0,%1}, {%2,%3}, {%4}, {%5,%6};" \
                 : "=r"(d0), "=r"(d1) \
                 : "r"(a0), "r"(a1), "r"(b0), "r"(0u), "r"(0u))

// PV MMA, f16 accumulate in-place (2x rate vs f32 accum)
#define MMA_16816_PV_F16(d0, d1, a0, a1, a2, a3, b0, b1) \
    asm volatile("mma.sync.aligned.m16n8k16.row.col.f16.f16.f16.f16 " \
                 "{%0,%1}, {%2,%3,%4,%5}, {%6,%7}, {%0,%1};" \
                 : "+r"(d0), "+r"(d1) \
                 : "r"(a0), "r"(a1), "r"(a2), "r"(a3), "r"(b0), "r"(b1))

#define EX2_F16X2(d, a) \
    asm("ex2.approx.f16x2 %0, %1;" : "=r"(d) : "r"(a))
#define HADD2(d, a, b) \
    asm("add.rn.f16x2 %0, %1, %2;" : "=r"(d) : "r"(a), "r"(b))

#define CP_ASYNC16(smem_addr, gptr) \
    asm volatile("cp.async.cg.shared.global [%0], [%1], 16;" \
                 :: "r"(smem_addr), "l"(gptr) : "memory")
#define CP_COMMIT() asm volatile("cp.async.commit_group;" ::: "memory")
#define CP_WAIT(n)  asm volatile("cp.async.wait_group %0;" :: "n"(n) : "memory")

// SMEM layout (static, double-buffered K/V)
#define SM_Q   0                    // 64 x 16B   (1KB)
#define SM_K0  1024                 // 128 x 16B  (2KB)
#define SM_K1  3072
#define SM_V0  5120                 // 128 x 128B (16KB)
#define SM_V1  21504
#define SM_BYTES 37888              // epilogue reuses [0,16KB) as O stage

// ============================================================================
// Kernel 1: 1x1-conv projections (round-8 version: f32x2 FMA, 8 chains,
//   2-way output split). blockIdx.y = half h.
// ============================================================================
__global__ __launch_bounds__(64) void proj_kernel(
    const float* __restrict__ x,
    const float* __restrict__ wq, const float* __restrict__ bq,
    const float* __restrict__ wk, const float* __restrict__ bk,
    const float* __restrict__ wv, const float* __restrict__ bv) {
    __shared__ __align__(16) float s_wv[32 * NC];
    __shared__ __align__(16) float s_wq[4 * NC];
    __shared__ __align__(16) float s_wk[4 * NC];
    __shared__ float s_bv[32], s_bq4[4], s_bk4[4];

    int tid = threadIdx.x;
    int h = blockIdx.y;

    for (int i = tid; i < 32 * NC; i += 64) s_wv[i] = wv[h * 32 * NC + i];
    for (int i = tid; i < 4 * NC; i += 64) {
        s_wq[i] = wq[h * 4 * NC + i];
        s_wk[i] = wk[h * 4 * NC + i];
    }
    if (tid < 32) s_bv[tid] = bv[h * 32 + tid];
    if (tid < 4) { s_bq4[tid] = bq[h * 4 + tid]; s_bk4[tid] = bk[h * 4 + tid]; }
    __syncthreads();

    int idx = blockIdx.x * 64 + tid;
    int n = idx & (NN - 1);
    int b = idx >> 12;

    const float* xp = x + (size_t)b * NC * NN + n;
    unsigned long long x2[32];
#pragma unroll
    for (int j = 0; j < 32; j++)
        x2[j] = pack2(xp[(size_t)(2 * j) * NN], xp[(size_t)(2 * j + 1) * NN]);

    __half* qo = g_q + (size_t)idx * ND;
    __half* ko = g_k + (size_t)idx * ND;
    __half* vo = g_v + (size_t)idx * NC;
    int swv = (n & 7) << 3;

#pragma unroll
    for (int og = 0; og < 2; og++) {
        unsigned long long aq[2][2] = {{0ull, 0ull}, {0ull, 0ull}};
        unsigned long long ak[2][2] = {{0ull, 0ull}, {0ull, 0ull}};
        const ulonglong2* wr0 = reinterpret_cast<const ulonglong2*>(s_wq + (2 * og) * NC);
        const ulonglong2* wr1 = reinterpret_cast<const ulonglong2*>(s_wq + (2 * og + 1) * NC);
        const ulonglong2* ur0 = reinterpret_cast<const ulonglong2*>(s_wk + (2 * og) * NC);
        const ulonglong2* ur1 = reinterpret_cast<const ulonglong2*>(s_wk + (2 * og + 1) * NC);
#pragma unroll
        for (int c4 = 0; c4 < 16; c4++) {
            ulonglong2 w;
            int p = c4 & 1;
            w = wr0[c4]; fma2(aq[0][p], w.x, x2[2 * c4]); fma2(aq[0][p], w.y, x2[2 * c4 + 1]);
            w = wr1[c4]; fma2(aq[1][p], w.x, x2[2 * c4]); fma2(aq[1][p], w.y, x2[2 * c4 + 1]);
            w = ur0[c4]; fma2(ak[0][p], w.x, x2[2 * c4]); fma2(ak[0][p], w.y, x2[2 * c4 + 1]);
            w = ur1[c4]; fma2(ak[1][p], w.x, x2[2 * c4]); fma2(ak[1][p], w.y, x2[2 * c4 + 1]);
        }
        float2 q0a = unpack2(aq[0][0]), q0b = unpack2(aq[0][1]);
        float2 q1a = unpack2(aq[1][0]), q1b = unpack2(aq[1][1]);
        float2 k0a = unpack2(ak[0][0]), k0b = unpack2(ak[0][1]);
        float2 k1a = unpack2(ak[1][0]), k1b = unpack2(ak[1][1]);
        float fq0 = (q0a.x + q0a.y + q0b.x + q0b.y + s_bq4[2 * og]) * LOG2E;
        float fq1 = (q1a.x + q1a.y + q1b.x + q1b.y + s_bq4[2 * og + 1]) * LOG2E;
        float fk0 = k0a.x + k0a.y + k0b.x + k0b.y + s_bk4[2 * og];
        float fk1 = k1a.x + k1a.y + k1b.x + k1b.y + s_bk4[2 * og + 1];
        *reinterpret_cast<__half2*>(qo + 4 * h + 2 * og) = __floats2half2_rn(fq0, fq1);
        *reinterpret_cast<__half2*>(ko + 4 * h + 2 * og) = __floats2half2_rn(fk0, fk1);
    }

    for (int g = 0; g < 8; g++) {
        int o = 32 * h + 4 * g;
        unsigned long long a0[2] = {0ull, 0ull}, a1[2] = {0ull, 0ull};
        unsigned long long a2[2] = {0ull, 0ull}, a3[2] = {0ull, 0ull};
        const ulonglong2* w0 = reinterpret_cast<const ulonglong2*>(s_wv + (4 * g) * NC);
        const ulonglong2* w1 = reinterpret_cast<const ulonglong2*>(s_wv + (4 * g + 1) * NC);
        const ulonglong2* w2 = reinterpret_cast<const ulonglong2*>(s_wv + (4 * g + 2) * NC);
        const ulonglong2* w3 = reinterpret_cast<const ulonglong2*>(s_wv + (4 * g + 3) * NC);
#pragma unroll
        for (int c4 = 0; c4 < 16; c4++) {
            ulonglong2 w;
            int p = c4 & 1;
            w = w0[c4]; fma2(a0[p], w.x, x2[2 * c4]); fma2(a0[p], w.y, x2[2 * c4 + 1]);
            w = w1[c4]; fma2(a1[p], w.x, x2[2 * c4]); fma2(a1[p], w.y, x2[2 * c4 + 1]);
            w = w2[c4]; fma2(a2[p], w.x, x2[2 * c4]); fma2(a2[p], w.y, x2[2 * c4 + 1]);
            w = w3[c4]; fma2(a3[p], w.x, x2[2 * c4]); fma2(a3[p], w.y, x2[2 * c4 + 1]);
        }
        float2 f0a = unpack2(a0[0]), f0b = unpack2(a0[1]);
        float2 f1a = unpack2(a1[0]), f1b = unpack2(a1[1]);
        float2 f2a = unpack2(a2[0]), f2b = unpack2(a2[1]);
        float2 f3a = unpack2(a3[0]), f3b = unpack2(a3[1]);
        float r0 = f0a.x + f0a.y + f0b.x + f0b.y + s_bv[4 * g];
        float r1 = f1a.x + f1a.y + f1b.x + f1b.y + s_bv[4 * g + 1];
        float r2 = f2a.x + f2a.y + f2b.x + f2b.y + s_bv[4 * g + 2];
        float r3 = f3a.x + f3a.y + f3b.x + f3b.y + s_bv[4 * g + 3];
        *reinterpret_cast<__half2*>(vo + (o ^ swv))       = __floats2half2_rn(r0, r1);
        *reinterpret_cast<__half2*>(vo + ((o + 2) ^ swv)) = __floats2half2_rn(r2, r3);
    }
}

// ============================================================================
// Kernel 2: flash attention partial, SPLIT=2. grid (64, 8, 2) = 1024 CTAs of
//   4 warps -> ~20 resident warps/SM (smem cap 5 CTAs). K=8 S-MMA, ex2 on
//   fragments, f16-PV flushed to fp32 per tile. Writes fp16 O partials + l.
// ============================================================================
__global__ __launch_bounds__(THREADS, 5) void attn_kernel() {
    __shared__ __align__(16) char smem[SM_BYTES];
    uint32_t sb = smem_u32(smem);

    int tid = threadIdx.x;
    int w = tid >> 5, l = tid & 31;
    int lr = l & 7, sub = l >> 3;
    int qr = w * 16;
    int b = blockIdx.y;
    int z = blockIdx.z;
    int i0 = blockIdx.x * TQ;
    int j_base = z * (NN / SPLIT);

    const uint4* gq4 = reinterpret_cast<const uint4*>(g_q) + (size_t)b * NN + i0;
    const uint4* gk4 = reinterpret_cast<const uint4*>(g_k) + (size_t)b * NN + j_base;
    const uint4* gv4 = reinterpret_cast<const uint4*>(g_v) + (size_t)b * NN * 8 + (size_t)j_base * 8;

    // prologue: stage Q + tile 0 (buffer 0)
    for (int t = tid; t < 64; t += THREADS)
        CP_ASYNC16(sb + SM_Q + (uint32_t)t * 16, gq4 + t);
    for (int t = tid; t < 128; t += THREADS)
        CP_ASYNC16(sb + SM_K0 + (uint32_t)t * 16, gk4 + t);
    for (int t = tid; t < 1024; t += THREADS)
        CP_ASYNC16(sb + SM_V0 + (uint32_t)t * 16, gv4 + t);
    CP_COMMIT();
    CP_WAIT(0);
    __syncthreads();

    uint32_t qaddr = sb + SM_Q + (uint32_t)(qr + (l & 15)) * 16;
    uint32_t koff = (uint32_t)(l & 15) * 16;
    uint32_t voff = (uint32_t)(lr + (sub & 1) * 8) * 128;
    uint32_t kb2[2] = { sb + SM_K0 + koff, sb + SM_K1 + koff };
    uint32_t vb2[2] = { sb + SM_V0 + voff, sb + SM_V1 + voff };
    int vsub = sub >> 1;

    uint32_t qa0, qa1;
    LDMATRIX_X2(qa0, qa1, qaddr);

    float o[32];
#pragma unroll
    for (int k = 0; k < 32; k++) o[k] = 0.f;
    float lsum0 = 0.f, lsum1 = 0.f;

    for (int t = 0; t < NT; t++) {
        if (t + 1 < NT) {
            uint32_t kd = (t & 1) ? SM_K0 : SM_K1;
            uint32_t vd = (t & 1) ? SM_V0 : SM_V1;
            const uint4* gk = gk4 + (t + 1) * 128;
            const uint4* gv = gv4 + (t + 1) * 1024;
            for (int u = tid; u < 128; u += THREADS)
                CP_ASYNC16(sb + kd + (uint32_t)u * 16, gk + u);
            for (int u = tid; u < 1024; u += THREADS)
                CP_ASYNC16(sb + vd + (uint32_t)u * 16, gv + u);
            CP_COMMIT();
        }
        if (t > 0) {
            if (t + 1 < NT) CP_WAIT(1); else CP_WAIT(0);
            __syncthreads();
        }

        uint32_t kbase = kb2[t & 1];
        uint32_t vbase = vb2[t & 1];
        uint32_t acc0 = 0, acc1 = 0;
        uint32_t o16[16];
#pragma unroll
        for (int k = 0; k < 16; k++) o16[k] = 0;

#pragma unroll
        for (int jt = 0; jt < 8; jt++) {           // 16 keys per step
            uint32_t kr0, kr1;
            LDMATRIX_X2(kr0, kr1, kbase + (uint32_t)jt * 256);

            uint32_t pa0, pa1, pa2, pa3;
            MMA_K8_S_F16(pa0, pa1, qa0, qa1, kr0);
            MMA_K8_S_F16(pa2, pa3, qa0, qa1, kr1);

            EX2_F16X2(pa0, pa0);
            EX2_F16X2(pa1, pa1);
            EX2_F16X2(pa2, pa2);
            EX2_F16X2(pa3, pa3);
            uint32_t h0, h1;
            HADD2(h0, pa0, pa2); HADD2(acc0, acc0, h0);
            HADD2(h1, pa1, pa3); HADD2(acc1, acc1, h1);

            uint32_t vrow = vbase + (uint32_t)jt * 2048;
#pragma unroll
            for (int ct = 0; ct < 8; ct += 2) {
                uint32_t vr0, vr1, vr2, vr3;
                uint32_t va = vrow + (uint32_t)(((ct + vsub) ^ lr) << 4);
                LDMATRIX_X4_T(vr0, vr1, vr2, vr3, va);
                MMA_16816_PV_F16(o16[ct * 2 + 0], o16[ct * 2 + 1],
                                 pa0, pa1, pa2, pa3, vr0, vr1);
                MMA_16816_PV_F16(o16[ct * 2 + 2], o16[ct * 2 + 3],
                                 pa0, pa1, pa2, pa3, vr2, vr3);
            }
        }

        // flush tile: f16x2 -> f32 accumulators
#pragma unroll
        for (int ct = 0; ct < 8; ct++) {
            float2 f0 = __half22float2(*reinterpret_cast<__half2*>(&o16[ct * 2]));
            float2 f1 = __half22float2(*reinterpret_cast<__half2*>(&o16[ct * 2 + 1]));
            o[ct * 4 + 0] += f0.x;
            o[ct * 4 + 1] += f0.y;
            o[ct * 4 + 2] += f1.x;
            o[ct * 4 + 3] += f1.y;
        }
        {
            float2 f0 = __half22float2(*reinterpret_cast<__half2*>(&acc0));
            float2 f1 = __half22float2(*reinterpret_cast<__half2*>(&acc1));
            lsum0 += f0.x + f0.y;
            lsum1 += f1.x + f1.y;
        }
        __syncthreads();
    }

    // quad reduce row sums; write l partials
    lsum0 += __shfl_xor_sync(0xffffffffu, lsum0, 1);
    lsum0 += __shfl_xor_sync(0xffffffffu, lsum0, 2);
    lsum1 += __shfl_xor_sync(0xffffffffu, lsum1, 1);
    lsum1 += __shfl_xor_sync(0xffffffffu, lsum1, 2);
    float* lp = g_l[z] + (size_t)b * NN + i0;
    if ((l & 3) == 0) {
        lp[qr + (l >> 2)]     = lsum0;
        lp[qr + (l >> 2) + 8] = lsum1;
    }

    // epilogue: stage O as [c][i] (64x64 f32 = 16KB), fp16 partial writes
    __syncthreads();
    float* so = reinterpret_cast<float*>(smem);
    int row0 = qr + (l >> 2);
    int cb = (l & 3) * 2;
#pragma unroll
    for (int ct = 0; ct < 8; ct++) {
        int c0 = ct * 8 + cb;
        so[c0 * 64 + row0]           = o[ct * 4 + 0];
        so[(c0 + 1) * 64 + row0]     = o[ct * 4 + 1];
        so[c0 * 64 + row0 + 8]       = o[ct * 4 + 2];
        so[(c0 + 1) * 64 + row0 + 8] = o[ct * 4 + 3];
    }
    __syncthreads();

    __half* gO = g_O[z] + (size_t)b * NC * NN + i0;
    const float4* so4 = reinterpret_cast<const float4*>(so);
    for (int t = tid; t < 1024; t += THREADS) {
        int c = t >> 4;
        int i = (t & 15) * 4;
        float4 v = so4[t];
        __half2 h0 = __floats2half2_rn(v.x, v.y);
        __half2 h1 = __floats2half2_rn(v.z, v.w);
        uint2 pk = make_uint2(*reinterpret_cast<uint32_t*>(&h0),
                              *reinterpret_cast<uint32_t*>(&h1));
        *reinterpret_cast<uint2*>(gO + (size_t)c * NN + i) = pk;
    }
}

// ============================================================================
// Kernel 3: combine split-K partials: out = gamma*(O0+O1)/(l0+l1) + x
// ============================================================================
__global__ __launch_bounds__(256) void combine_kernel(
    const float* __restrict__ x,
    const float* __restrict__ gamma,
    float* __restrict__ out) {
    int t = blockIdx.x * 256 + threadIdx.x;
    int b = t >> 16;
    int rem = t & 65535;
    int c = rem >> 10;
    int i = (rem & 1023) << 2;
    size_t oidx = ((size_t)b * NC + c) * NN + i;
    size_t lidx = (size_t)b * NN + i;

    const __half2* p0 = reinterpret_cast<const __half2*>(&g_O[0][oidx]);
    const __half2* p1 = reinterpret_cast<const __half2*>(&g_O[1][oidx]);
    float2 a0 = __half22float2(p0[0]), a1 = __half22float2(p0[1]);
    float2 b0 = __half22float2(p1[0]), b1 = __half22float2(p1[1]);
    float4 l0 = *reinterpret_cast<const float4*>(&g_l[0][lidx]);
    float4 l1 = *reinterpret_cast<const float4*>(&g_l[1][lidx]);
    float4 xr = *reinterpret_cast<const float4*>(&x[oidx]);
    float g = __ldg(gamma);

    float4 r;
    r.x = g * (a0.x + b0.x) / (l0.x + l1.x) + xr.x;
    r.y = g * (a0.y + b0.y) / (l0.y + l1.y) + xr.y;
    r.z = g * (a1.x + b1.x) / (l0.z + l1.z) + xr.z;
    r.w = g * (a1.y + b1.y) / (l0.w + l1.w) + xr.w;
    *reinterpret_cast<float4*>(&out[oidx]) = r;
}

extern "C" void kernel_launch(void* const* d_in, const int* in_sizes, int n_in,
                              void* d_out, int out_size) {
    const float* x     = (const float*)d_in[0];
    const float* wq    = (const float*)d_in[1];
    const float* bq    = (const float*)d_in[2];
    const float* wk    = (const float*)d_in[3];
    const float* bk    = (const float*)d_in[4];
    const float* wv    = (const float*)d_in[5];
    const float* bv    = (const float*)d_in[6];
    const float* gamma = (const float*)d_in[7];
    float* out = (float*)d_out;

    proj_kernel<<<dim3(NB * NN / 64, 2), 64>>>(x, wq, bq, wk, bk, wv, bv);
    attn_kernel<<<dim3(NN / TQ, NB, SPLIT), THREADS>>>();
    combine_kernel<<<NB * NC * NN / 4 / 256, 256>>>(x, gamma, out);
}

// round 10
// speedup vs baseline: 1.4060x; 1.1003x over previous
#include <cuda_runtime.h>
#include <cuda_fp16.h>
#include <cstdint>

// Problem constants
#define NB 8      // batch
#define NC 64     // channels
#define NN 4096   // H*W
#define ND 8      // qk head dim (exact, no padding: m16n8k8)
#define TQ 64     // queries per CTA (4 warps x 16 rows)
#define TK 128    // keys per tile
#define THREADS 128
#define SPLIT 2
#define NT (NN / TK / SPLIT)   // 16 key tiles per CTA

#define LOG2E 1.4426950408889634f

// Scratch (__device__ globals; no allocation allowed)
// g_q/g_k: [B, N, 8] fp16 (16B rows). q pre-scaled by log2(e).
// g_v:     [B, N, 64] fp16, c-index XOR-swizzled by (n&7)*8 (128B rows)
__device__ __align__(16) __half g_q[NB * NN * ND];
__device__ __align__(16) __half g_k[NB * NN * ND];
__device__ __align__(16) __half g_v[NB * NN * NC];
// split-K partials (fp16 O: errors damped ~1000x by the +x residual)
__device__ __align__(16) __half g_O[SPLIT][NB * NC * NN];
__device__ __align__(16) float  g_l[SPLIT][NB * NN];

// ---------------------------------------------------------------------------
// Inline PTX
// ---------------------------------------------------------------------------
__device__ __forceinline__ uint32_t smem_u32(const void* p) {
    uint32_t a;
    asm("{ .reg .u64 t; cvta.to.shared.u64 t, %1; cvt.u32.u64 %0, t; }"
        : "=r"(a) : "l"(p));
    return a;
}

#define LDMATRIX_X2(r0, r1, addr) \
    asm volatile("ldmatrix.sync.aligned.m8n8.x2.shared.b16 {%0,%1}, [%2];" \
                 : "=r"(r0), "=r"(r1) : "r"(addr))

#define LDMATRIX_X4(r0, r1, r2, r3, addr) \
    asm volatile("ldmatrix.sync.aligned.m8n8.x4.shared.b16 {%0,%1,%2,%3}, [%4];" \
                 : "=r"(r0), "=r"(r1), "=r"(r2), "=r"(r3) : "r"(addr))

#define LDMATRIX_X4_T(r0, r1, r2, r3, addr) \
    asm volatile("ldmatrix.sync.aligned.m8n8.x4.trans.shared.b16 {%0,%1,%2,%3}, [%4];" \
                 : "=r"(r0), "=r"(r1), "=r"(r2), "=r"(r3) : "r"(addr))

// S = q.k, K=8, f16 accum; C-fragment == PV A-fragment k-slots (FA2 reuse)
#define MMA_K8_S_F16(d0, d1, a0, a1, b0) \
    asm volatile("mma.sync.aligned.m16n8k8.row.col.f16.f16.f16.f16 " \
                 "{%0,%1}, {%2,%3}, {%4}, {%5,%6};" \
                 : "=r"(d0), "=r"(d1) \
                 : "r"(a0), "r"(a1), "r"(b0), "r"(0u), "r"(0u))

// k16 MMA, f16 accumulate in-place (used for PV and for the proj GEMM)
#define MMA_16816_PV_F16(d0, d1, a0, a1, a2, a3, b0, b1) \
    asm volatile("mma.sync.aligned.m16n8k16.row.col.f16.f16.f16.f16 " \
                 "{%0,%1}, {%2,%3,%4,%5}, {%6,%7}, {%0,%1};" \
                 : "+r"(d0), "+r"(d1) \
                 : "r"(a0), "r"(a1), "r"(a2), "r"(a3), "r"(b0), "r"(b1))

#define EX2_F16X2(d, a) \
    asm("ex2.approx.f16x2 %0, %1;" : "=r"(d) : "r"(a))
#define HADD2(d, a, b) \
    asm("add.rn.f16x2 %0, %1, %2;" : "=r"(d) : "r"(a), "r"(b))

#define CP_ASYNC16(smem_addr, gptr) \
    asm volatile("cp.async.cg.shared.global [%0], [%1], 16;" \
                 :: "r"(smem_addr), "l"(gptr) : "memory")
#define CP_COMMIT() asm volatile("cp.async.commit_group;" ::: "memory")
#define CP_WAIT(n)  asm volatile("cp.async.wait_group %0;" :: "n"(n) : "memory")

// SMEM layout for attn (static, double-buffered K/V)
#define SM_Q   0                    // 64 x 16B   (1KB)
#define SM_K0  1024                 // 128 x 16B  (2KB)
#define SM_K1  3072
#define SM_V0  5120                 // 128 x 128B (16KB)
#define SM_V1  21504
#define SM_BYTES 37888              // epilogue reuses [0,16KB) as O stage

// ============================================================================
// Kernel 1: projections as a tensor-core GEMM.
//   One CTA = 64 positions of one batch. A = x^T tile (m=pos, k=ch) via
//   ldmatrix.x4.trans on a swizzled [ch rows x 64 pos] fp16 tile (mirrors the
//   proven V pattern). B = W rows via non-trans ldmatrix.x4 (mirrors the K
//   pattern). f16-accum MMAs with bias preloaded in the C fragment.
// ============================================================================
__global__ __launch_bounds__(THREADS) void proj_kernel(
    const float* __restrict__ x,
    const float* __restrict__ wq, const float* __restrict__ bq,
    const float* __restrict__ wk, const float* __restrict__ bk,
    const float* __restrict__ wv, const float* __restrict__ bv) {
    __shared__ __align__(16) __half s_x[64 * 64];    // [ch][pos] swizzled, 8KB
    __shared__ __align__(16) __half s_wv[64 * 64];   // [out][ch] swizzled, 8KB
    __shared__ __align__(16) __half s_wq[8 * 64];    // 1KB (pre-scaled log2e)
    __shared__ __align__(16) __half s_wk[8 * 64];    // 1KB
    __shared__ float s_bv[64], s_bq[8], s_bk[8];

    int tid = threadIdx.x;
    int b = blockIdx.x >> 6;
    int n0 = (blockIdx.x & 63) * 64;
    char* sxc = reinterpret_cast<char*>(s_x);
    char* svc = reinterpret_cast<char*>(s_wv);
    char* sqc = reinterpret_cast<char*>(s_wq);
    char* skc = reinterpret_cast<char*>(s_wk);

    // ---- stage x tile [64 ch x 64 pos] fp32 -> fp16, swizzled ----
    const float4* x4p = reinterpret_cast<const float4*>(x + (size_t)b * NC * NN + n0);
    // row c at x + b*C*N + c*N + n0 : as float4, row stride NN/4
    for (int t = tid; t < 1024; t += THREADS) {
        int c = t >> 4, p4 = t & 15;
        float4 w = x4p[(size_t)c * (NN / 4) + p4];
        uint32_t off = (uint32_t)(c * 128 + ((8 * p4) ^ ((c & 7) << 4)));
        __half2 h0 = __floats2half2_rn(w.x, w.y);
        __half2 h1 = __floats2half2_rn(w.z, w.w);
        *reinterpret_cast<__half2*>(sxc + off)     = h0;
        *reinterpret_cast<__half2*>(sxc + off + 4) = h1;
    }
    // ---- stage W (fp32 -> fp16, swizzled rows) ----
    const float4* wv4 = reinterpret_cast<const float4*>(wv);
    for (int t = tid; t < 1024; t += THREADS) {
        int r = t >> 4, c4 = t & 15;
        float4 w = wv4[t];
        uint32_t off = (uint32_t)(r * 128 + ((8 * c4) ^ ((r & 7) << 4)));
        *reinterpret_cast<__half2*>(svc + off)     = __floats2half2_rn(w.x, w.y);
        *reinterpret_cast<__half2*>(svc + off + 4) = __floats2half2_rn(w.z, w.w);
    }
    const float4* wq4 = reinterpret_cast<const float4*>(wq);
    const float4* wk4 = reinterpret_cast<const float4*>(wk);
    for (int t = tid; t < 128; t += THREADS) {
        int r = t >> 4, c4 = t & 15;
        uint32_t off = (uint32_t)(r * 128 + ((8 * c4) ^ ((r & 7) << 4)));
        float4 a = wq4[t];
        *reinterpret_cast<__half2*>(sqc + off)     = __floats2half2_rn(a.x * LOG2E, a.y * LOG2E);
        *reinterpret_cast<__half2*>(sqc + off + 4) = __floats2half2_rn(a.z * LOG2E, a.w * LOG2E);
        float4 k = wk4[t];
        *reinterpret_cast<__half2*>(skc + off)     = __floats2half2_rn(k.x, k.y);
        *reinterpret_cast<__half2*>(skc + off + 4) = __floats2half2_rn(k.z, k.w);
    }
    if (tid < 64) s_bv[tid] = bv[tid];
    if (tid < 8) { s_bq[tid] = bq[tid] * LOG2E; s_bk[tid] = bk[tid]; }
    __syncthreads();

    int wm = tid >> 5, l = tid & 31;
    int mat = l >> 3, j = l & 7;
    int cpr = l & 3, r = l >> 2;
    uint32_t sx = smem_u32(s_x), sv = smem_u32(s_wv);
    uint32_t sq = smem_u32(s_wq), sk = smem_u32(s_wk);
    uint32_t xorj = (uint32_t)(j << 4);

    // ---- A fragments: 4 k-chunks of 16 ch (m = this warp's 16 positions) ----
    uint32_t a[4][4];
#pragma unroll
    for (int kc = 0; kc < 4; kc++) {
        uint32_t row = (uint32_t)(kc * 16 + ((mat >> 1) << 3) + j);        // ch
        uint32_t posb = (uint32_t)((wm << 5) + ((mat & 1) << 4));          // pos bytes
        LDMATRIX_X4_T(a[kc][0], a[kc][1], a[kc][2], a[kc][3],
                      sx + row * 128 + (posb ^ xorj));
    }

    // ---- accumulators preloaded with bias (per-n, m-independent) ----
    uint32_t vacc[8][2];
#pragma unroll
    for (int nb = 0; nb < 8; nb++) {
        __half2 hb = __floats2half2_rn(s_bv[nb * 8 + 2 * cpr], s_bv[nb * 8 + 2 * cpr + 1]);
        vacc[nb][0] = vacc[nb][1] = *reinterpret_cast<uint32_t*>(&hb);
    }
    uint32_t qacc[2], kacc[2];
    {
        __half2 hq = __floats2half2_rn(s_bq[2 * cpr], s_bq[2 * cpr + 1]);
        __half2 hk = __floats2half2_rn(s_bk[2 * cpr], s_bk[2 * cpr + 1]);
        qacc[0] = qacc[1] = *reinterpret_cast<uint32_t*>(&hq);
        kacc[0] = kacc[1] = *reinterpret_cast<uint32_t*>(&hk);
    }

    // ---- v GEMM: 8 n-blocks x 4 k-chunks ----
#pragma unroll
    for (int nbp = 0; nbp < 4; nbp++) {
#pragma unroll
        for (int kc = 0; kc < 4; kc++) {
            uint32_t row = (uint32_t)(nbp * 16 + ((mat >> 1) << 3) + j);   // out
            uint32_t chb = (uint32_t)((kc << 5) + ((mat & 1) << 4));
            uint32_t w0, w1, w2, w3;
            LDMATRIX_X4(w0, w1, w2, w3, sv + row * 128 + (chb ^ xorj));
            MMA_16816_PV_F16(vacc[2 * nbp][0], vacc[2 * nbp][1],
                             a[kc][0], a[kc][1], a[kc][2], a[kc][3], w0, w1);
            MMA_16816_PV_F16(vacc[2 * nbp + 1][0], vacc[2 * nbp + 1][1],
                             a[kc][0], a[kc][1], a[kc][2], a[kc][3], w2, w3);
        }
    }
    // ---- q/k GEMMs: 1 n-block x 4 k-chunks each ----
#pragma unroll
    for (int kc2 = 0; kc2 < 2; kc2++) {
        uint32_t chb = (uint32_t)((kc2 << 6) + ((mat >> 1) << 5) + ((mat & 1) << 4));
        uint32_t addr_off = (uint32_t)(j * 128) + (chb ^ xorj);
        uint32_t q0, q1, q2, q3;
        LDMATRIX_X4(q0, q1, q2, q3, sq + addr_off);
        MMA_16816_PV_F16(qacc[0], qacc[1],
                         a[2 * kc2][0], a[2 * kc2][1], a[2 * kc2][2], a[2 * kc2][3], q0, q1);
        MMA_16816_PV_F16(qacc[0], qacc[1],
                         a[2 * kc2 + 1][0], a[2 * kc2 + 1][1], a[2 * kc2 + 1][2], a[2 * kc2 + 1][3], q2, q3);
        uint32_t k0, k1, k2, k3;
        LDMATRIX_X4(k0, k1, k2, k3, sk + addr_off);
        MMA_16816_PV_F16(kacc[0], kacc[1],
                         a[2 * kc2][0], a[2 * kc2][1], a[2 * kc2][2], a[2 * kc2][3], k0, k1);
        MMA_16816_PV_F16(kacc[0], kacc[1],
                         a[2 * kc2 + 1][0], a[2 * kc2 + 1][1], a[2 * kc2 + 1][2], a[2 * kc2 + 1][3], k2, k3);
    }

    // ---- epilogue: direct half2 stores in the attn-consumable layouts ----
    int pos0 = wm * 16 + r;
    int pos1 = pos0 + 8;
    size_t nidx0 = (size_t)b * NN + n0 + pos0;
    size_t nidx1 = (size_t)b * NN + n0 + pos1;
    int sw0 = (pos0 & 7) << 3, sw1 = (pos1 & 7) << 3;
    __half* vo0 = g_v + nidx0 * NC;
    __half* vo1 = g_v + nidx1 * NC;
#pragma unroll
    for (int nb = 0; nb < 8; nb++) {
        int ch = nb * 8 + 2 * cpr;
        *reinterpret_cast<uint32_t*>(vo0 + (ch ^ sw0)) = vacc[nb][0];
        *reinterpret_cast<uint32_t*>(vo1 + (ch ^ sw1)) = vacc[nb][1];
    }
    *reinterpret_cast<uint32_t*>(g_q + nidx0 * ND + 2 * cpr) = qacc[0];
    *reinterpret_cast<uint32_t*>(g_q + nidx1 * ND + 2 * cpr) = qacc[1];
    *reinterpret_cast<uint32_t*>(g_k + nidx0 * ND + 2 * cpr) = kacc[0];
    *reinterpret_cast<uint32_t*>(g_k + nidx1 * ND + 2 * cpr) = kacc[1];
}

// ============================================================================
// Kernel 2: flash attention partial, SPLIT=2 (round-9, verified).
// ============================================================================
__global__ __launch_bounds__(THREADS, 5) void attn_kernel() {
    __shared__ __align__(16) char smem[SM_BYTES];
    uint32_t sb = smem_u32(smem);

    int tid = threadIdx.x;
    int w = tid >> 5, l = tid & 31;
    int lr = l & 7, sub = l >> 3;
    int qr = w * 16;
    int b = blockIdx.y;
    int z = blockIdx.z;
    int i0 = blockIdx.x * TQ;
    int j_base = z * (NN / SPLIT);

    const uint4* gq4 = reinterpret_cast<const uint4*>(g_q) + (size_t)b * NN + i0;
    const uint4* gk4 = reinterpret_cast<const uint4*>(g_k) + (size_t)b * NN + j_base;
    const uint4* gv4 = reinterpret_cast<const uint4*>(g_v) + (size_t)b * NN * 8 + (size_t)j_base * 8;

    for (int t = tid; t < 64; t += THREADS)
        CP_ASYNC16(sb + SM_Q + (uint32_t)t * 16, gq4 + t);
    for (int t = tid; t < 128; t += THREADS)
        CP_ASYNC16(sb + SM_K0 + (uint32_t)t * 16, gk4 + t);
    for (int t = tid; t < 1024; t += THREADS)
        CP_ASYNC16(sb + SM_V0 + (uint32_t)t * 16, gv4 + t);
    CP_COMMIT();
    CP_WAIT(0);
    __syncthreads();

    uint32_t qaddr = sb + SM_Q + (uint32_t)(qr + (l & 15)) * 16;
    uint32_t koff = (uint32_t)(l & 15) * 16;
    uint32_t voff = (uint32_t)(lr + (sub & 1) * 8) * 128;
    uint32_t kb2[2] = { sb + SM_K0 + koff, sb + SM_K1 + koff };
    uint32_t vb2[2] = { sb + SM_V0 + voff, sb + SM_V1 + voff };
    int vsub = sub >> 1;

    uint32_t qa0, qa1;
    LDMATRIX_X2(qa0, qa1, qaddr);

    float o[32];
#pragma unroll
    for (int k = 0; k < 32; k++) o[k] = 0.f;
    float lsum0 = 0.f, lsum1 = 0.f;

    for (int t = 0; t < NT; t++) {
        if (t + 1 < NT) {
            uint32_t kd = (t & 1) ? SM_K0 : SM_K1;
            uint32_t vd = (t & 1) ? SM_V0 : SM_V1;
            const uint4* gk = gk4 + (t + 1) * 128;
            const uint4* gv = gv4 + (t + 1) * 1024;
            for (int u = tid; u < 128; u += THREADS)
                CP_ASYNC16(sb + kd + (uint32_t)u * 16, gk + u);
            for (int u = tid; u < 1024; u += THREADS)
                CP_ASYNC16(sb + vd + (uint32_t)u * 16, gv + u);
            CP_COMMIT();
        }
        if (t > 0) {
            if (t + 1 < NT) CP_WAIT(1); else CP_WAIT(0);
            __syncthreads();
        }

        uint32_t kbase = kb2[t & 1];
        uint32_t vbase = vb2[t & 1];
        uint32_t acc0 = 0, acc1 = 0;
        uint32_t o16[16];
#pragma unroll
        for (int k = 0; k < 16; k++) o16[k] = 0;

#pragma unroll
        for (int jt = 0; jt < 8; jt++) {
            uint32_t kr0, kr1;
            LDMATRIX_X2(kr0, kr1, kbase + (uint32_t)jt * 256);

            uint32_t pa0, pa1, pa2, pa3;
            MMA_K8_S_F16(pa0, pa1, qa0, qa1, kr0);
            MMA_K8_S_F16(pa2, pa3, qa0, qa1, kr1);

            EX2_F16X2(pa0, pa0);
            EX2_F16X2(pa1, pa1);
            EX2_F16X2(pa2, pa2);
            EX2_F16X2(pa3, pa3);
            uint32_t h0, h1;
            HADD2(h0, pa0, pa2); HADD2(acc0, acc0, h0);
            HADD2(h1, pa1, pa3); HADD2(acc1, acc1, h1);

            uint32_t vrow = vbase + (uint32_t)jt * 2048;
#pragma unroll
            for (int ct = 0; ct < 8; ct += 2) {
                uint32_t vr0, vr1, vr2, vr3;
                uint32_t va = vrow + (uint32_t)(((ct + vsub) ^ lr) << 4);
                LDMATRIX_X4_T(vr0, vr1, vr2, vr3, va);
                MMA_16816_PV_F16(o16[ct * 2 + 0], o16[ct * 2 + 1],
                                 pa0, pa1, pa2, pa3, vr0, vr1);
                MMA_16816_PV_F16(o16[ct * 2 + 2], o16[ct * 2 + 3],
                                 pa0, pa1, pa2, pa3, vr2, vr3);
            }
        }

#pragma unroll
        for (int ct = 0; ct < 8; ct++) {
            float2 f0 = __half22float2(*reinterpret_cast<__half2*>(&o16[ct * 2]));
            float2 f1 = __half22float2(*reinterpret_cast<__half2*>(&o16[ct * 2 + 1]));
            o[ct * 4 + 0] += f0.x;
            o[ct * 4 + 1] += f0.y;
            o[ct * 4 + 2] += f1.x;
            o[ct * 4 + 3] += f1.y;
        }
        {
            float2 f0 = __half22float2(*reinterpret_cast<__half2*>(&acc0));
            float2 f1 = __half22float2(*reinterpret_cast<__half2*>(&acc1));
            lsum0 += f0.x + f0.y;
            lsum1 += f1.x + f1.y;
        }
        __syncthreads();
    }

    lsum0 += __shfl_xor_sync(0xffffffffu, lsum0, 1);
    lsum0 += __shfl_xor_sync(0xffffffffu, lsum0, 2);
    lsum1 += __shfl_xor_sync(0xffffffffu, lsum1, 1);
    lsum1 += __shfl_xor_sync(0xffffffffu, lsum1, 2);
    float* lp = g_l[z] + (size_t)b * NN + i0;
    if ((l & 3) == 0) {
        lp[qr + (l >> 2)]     = lsum0;
        lp[qr + (l >> 2) + 8] = lsum1;
    }

    __syncthreads();
    float* so = reinterpret_cast<float*>(smem);
    int row0 = qr + (l >> 2);
    int cb = (l & 3) * 2;
#pragma unroll
    for (int ct = 0; ct < 8; ct++) {
        int c0 = ct * 8 + cb;
        so[c0 * 64 + row0]           = o[ct * 4 + 0];
        so[(c0 + 1) * 64 + row0]     = o[ct * 4 + 1];
        so[c0 * 64 + row0 + 8]       = o[ct * 4 + 2];
        so[(c0 + 1) * 64 + row0 + 8] = o[ct * 4 + 3];
    }
    __syncthreads();

    __half* gO = g_O[z] + (size_t)b * NC * NN + i0;
    const float4* so4 = reinterpret_cast<const float4*>(so);
    for (int t = tid; t < 1024; t += THREADS) {
        int c = t >> 4;
        int i = (t & 15) * 4;
        float4 v = so4[t];
        __half2 h0 = __floats2half2_rn(v.x, v.y);
        __half2 h1 = __floats2half2_rn(v.z, v.w);
        uint2 pk = make_uint2(*reinterpret_cast<uint32_t*>(&h0),
                              *reinterpret_cast<uint32_t*>(&h1));
        *reinterpret_cast<uint2*>(gO + (size_t)c * NN + i) = pk;
    }
}

// ============================================================================
// Kernel 3: combine split-K partials: out = gamma*(O0+O1)/(l0+l1) + x
// ============================================================================
__global__ __launch_bounds__(256) void combine_kernel(
    const float* __restrict__ x,
    const float* __restrict__ gamma,
    float* __restrict__ out) {
    int t = blockIdx.x * 256 + threadIdx.x;
    int b = t >> 16;
    int rem = t & 65535;
    int c = rem >> 10;
    int i = (rem & 1023) << 2;
    size_t oidx = ((size_t)b * NC + c) * NN + i;
    size_t lidx = (size_t)b * NN + i;

    const __half2* p0 = reinterpret_cast<const __half2*>(&g_O[0][oidx]);
    const __half2* p1 = reinterpret_cast<const __half2*>(&g_O[1][oidx]);
    float2 a0 = __half22float2(p0[0]), a1 = __half22float2(p0[1]);
    float2 b0 = __half22float2(p1[0]), b1 = __half22float2(p1[1]);
    float4 l0 = *reinterpret_cast<const float4*>(&g_l[0][lidx]);
    float4 l1 = *reinterpret_cast<const float4*>(&g_l[1][lidx]);
    float4 xr = *reinterpret_cast<const float4*>(&x[oidx]);
    float g = __ldg(gamma);

    float4 r;
    r.x = g * (a0.x + b0.x) / (l0.x + l1.x) + xr.x;
    r.y = g * (a0.y + b0.y) / (l0.y + l1.y) + xr.y;
    r.z = g * (a1.x + b1.x) / (l0.z + l1.z) + xr.z;
    r.w = g * (a1.y + b1.y) / (l0.w + l1.w) + xr.w;
    *reinterpret_cast<float4*>(&out[oidx]) = r;
}

extern "C" void kernel_launch(void* const* d_in, const int* in_sizes, int n_in,
                              void* d_out, int out_size) {
    const float* x     = (const float*)d_in[0];
    const float* wq    = (const float*)d_in[1];
    const float* bq    = (const float*)d_in[2];
    const float* wk    = (const float*)d_in[3];
    const float* bk    = (const float*)d_in[4];
    const float* wv    = (const float*)d_in[5];
    const float* bv    = (const float*)d_in[6];
    const float* gamma = (const float*)d_in[7];
    float* out = (float*)d_out;

    proj_kernel<<<NB * NN / 64, THREADS>>>(x, wq, bq, wk, bk, wv, bv);
    attn_kernel<<<dim3(NN / TQ, NB, SPLIT), THREADS>>>();
    combine_kernel<<<NB * NC * NN / 4 / 256, 256>>>(x, gamma, out);
}